// round 3
// baseline (speedup 1.0000x reference)
#include <cuda_runtime.h>
#include <cstdint>

// ---------------- problem constants (compile-time) ----------------
#define NQ      13294          // 100*100 + 50*50 + 25*25 + 13*13
#define BS      2
#define M_TOT   (BS * NQ)      // 26588
#define EMBED   256
#define HEADS   8
#define DIM     32
#define LEVELS  4
#define POINTS  4

__device__ __constant__ int c_Wl[LEVELS]    = {100, 50, 25, 13};
__device__ __constant__ int c_Hl[LEVELS]    = {100, 50, 25, 13};
__device__ __constant__ int c_start[LEVELS] = {0, 10000, 12500, 13125};

// ---------------- scratch (static device memory, no allocation) ----------------
__device__ float g_value[(size_t)M_TOT * EMBED];   // (b,q,heads,dim)
__device__ float g_off  [(size_t)M_TOT * 256];     // (b,q,heads,levels,points,2)
__device__ float g_attn [(size_t)M_TOT * 128];     // (b,q,heads,16) raw logits
__device__ float g_acc  [(size_t)M_TOT * EMBED];   // sampled output

// ---------------- GEMM: C = A @ B + bias (+ residual), fp32 ----------------
// A: MxK row-major, B: KxN row-major. TILE 128x128x16, 256 threads, 8x8 microtile.
#define TM 128
#define TN 128
#define TK 16

__global__ void __launch_bounds__(256, 2)
gemm_bias_kernel(const float* __restrict__ A,
                 const float* __restrict__ B,
                 const float* __restrict__ bias,
                 const float* __restrict__ resid,
                 float* __restrict__ C,
                 int M, int N, int K) {
    __shared__ float As[TK][TM + 4];   // +4 keeps 16B alignment of rows; 2-way STS conflict only
    __shared__ float Bs[TK][TN];

    const int tid = threadIdx.x;
    const int m0  = blockIdx.y * TM;
    const int n0  = blockIdx.x * TN;
    const int ty  = tid >> 4;          // 0..15 -> 8 rows each
    const int tx  = tid & 15;          // 0..15 -> 8 cols each

    float c[8][8];
#pragma unroll
    for (int i = 0; i < 8; i++)
#pragma unroll
        for (int j = 0; j < 8; j++) c[i][j] = 0.f;

    // A-tile: thread loads 8 consecutive k at row a_m (128 rows x 16 k)
    const int a_m = tid >> 1;          // 0..127
    const int a_k = (tid & 1) << 3;    // 0 or 8
    // B-tile: thread loads 4 cols at rows b_k and b_k+8 (16 k x 128 n)
    const int b_k = tid >> 5;          // 0..7
    const int b_n = (tid & 31) << 2;   // 0..124

    const int  gm_a = m0 + a_m;
    const bool a_ok = (gm_a < M);
    const float* Arow = A + (size_t)gm_a * K + a_k;

    for (int k0 = 0; k0 < K; k0 += TK) {
        float4 v0 = make_float4(0.f, 0.f, 0.f, 0.f);
        float4 v1 = make_float4(0.f, 0.f, 0.f, 0.f);
        if (a_ok) {
            v0 = *reinterpret_cast<const float4*>(Arow + k0);
            v1 = *reinterpret_cast<const float4*>(Arow + k0 + 4);
        }
        float4 b0 = *reinterpret_cast<const float4*>(&B[(size_t)(k0 + b_k) * N + n0 + b_n]);
        float4 b1 = *reinterpret_cast<const float4*>(&B[(size_t)(k0 + b_k + 8) * N + n0 + b_n]);

        As[a_k + 0][a_m] = v0.x;
        As[a_k + 1][a_m] = v0.y;
        As[a_k + 2][a_m] = v0.z;
        As[a_k + 3][a_m] = v0.w;
        As[a_k + 4][a_m] = v1.x;
        As[a_k + 5][a_m] = v1.y;
        As[a_k + 6][a_m] = v1.z;
        As[a_k + 7][a_m] = v1.w;
        *reinterpret_cast<float4*>(&Bs[b_k][b_n])     = b0;
        *reinterpret_cast<float4*>(&Bs[b_k + 8][b_n]) = b1;
        __syncthreads();

#pragma unroll
        for (int kk = 0; kk < TK; kk++) {
            float4 a0 = *reinterpret_cast<const float4*>(&As[kk][ty << 3]);
            float4 a1 = *reinterpret_cast<const float4*>(&As[kk][(ty << 3) + 4]);
            float4 bb0 = *reinterpret_cast<const float4*>(&Bs[kk][tx << 3]);
            float4 bb1 = *reinterpret_cast<const float4*>(&Bs[kk][(tx << 3) + 4]);
            float a_[8] = {a0.x, a0.y, a0.z, a0.w, a1.x, a1.y, a1.z, a1.w};
            float b_[8] = {bb0.x, bb0.y, bb0.z, bb0.w, bb1.x, bb1.y, bb1.z, bb1.w};
#pragma unroll
            for (int i = 0; i < 8; i++)
#pragma unroll
                for (int j = 0; j < 8; j++) c[i][j] = fmaf(a_[i], b_[j], c[i][j]);
        }
        __syncthreads();
    }

#pragma unroll
    for (int i = 0; i < 8; i++) {
        int gm = m0 + (ty << 3) + i;
        if (gm >= M) continue;
#pragma unroll
        for (int j = 0; j < 8; j++) {
            int gn = n0 + (tx << 3) + j;
            float v = c[i][j] + bias[gn];
            if (resid) v += resid[(size_t)gm * N + gn];
            C[(size_t)gm * N + gn] = v;
        }
    }
}

// ---------------- sampling kernel ----------------
// block = one (b,q) row.
// Scalar phase: threads 0..127, one per (head,point): fused softmax weight,
// 4 corner channel-base indices (validity as -1), 4 premultiplied bilinear
// weights -> shared memory.
// Gather phase: warp = head; each warp-quarter (8 lanes) owns one corner;
// lane loads float4 (4 channels). Butterfly-reduce across the 4 quarters.
struct IW { int idx; float w; };

__global__ void msda_sample_kernel(const float* __restrict__ ref,
                                   const float* __restrict__ off,
                                   const float* __restrict__ logits,
                                   const float* __restrict__ value,
                                   float* __restrict__ acc) {
    __shared__ IW s_iw[128][4];   // [(head,point)][corner]

    const int row = blockIdx.x;
    const int tid = threadIdx.x;
    const int vbase = (row >= NQ) ? NQ : 0;   // b * NQ

    if (tid < 128) {
        const int head = tid >> 4;
        const int i    = tid & 15;     // (level,point)
        const int l    = i >> 2;
        const int Wl = c_Wl[l], Hl = c_Hl[l];

        // softmax across the 16-thread group (contiguous lanes -> width-16 shfl)
        float lg = __ldg(logits + (size_t)row * 128 + tid);
        float mx = lg;
#pragma unroll
        for (int o = 8; o >= 1; o >>= 1)
            mx = fmaxf(mx, __shfl_xor_sync(0xffffffffu, mx, o, 16));
        float e = __expf(lg - mx);
        float s = e;
#pragma unroll
        for (int o = 8; o >= 1; o >>= 1)
            s += __shfl_xor_sync(0xffffffffu, s, o, 16);
        const float w = e * __frcp_rn(s);

        const float rx = __ldg(ref + (size_t)row * 8 + 2 * l + 0) * (float)Wl - 0.5f;
        const float ry = __ldg(ref + (size_t)row * 8 + 2 * l + 1) * (float)Hl - 0.5f;
        const float2 o2 = *reinterpret_cast<const float2*>(off + (size_t)row * 256 + head * 32 + 2 * i);
        const float x = rx + o2.x;
        const float y = ry + o2.y;

        const float xf = floorf(x), yf = floorf(y);
        const int x0 = (int)xf, y0 = (int)yf;
        const float lx = x - xf, ly = y - yf;

        const bool yin0 = (y0 >= 0) & (y0 < Hl);
        const bool yin1 = (y0 + 1 >= 0) & (y0 + 1 < Hl);
        const bool xin0 = (x0 >= 0) & (x0 < Wl);
        const bool xin1 = (x0 + 1 >= 0) & (x0 + 1 < Wl);

        const int base = vbase + c_start[l];
        const int r0 = (base + y0 * Wl) * 256 + head * 32;
        const int r1 = r0 + Wl * 256;

        IW c0, c1, c2, c3;
        c0.idx = (yin0 && xin0) ? r0 + x0 * 256       : -1;
        c1.idx = (yin0 && xin1) ? r0 + (x0 + 1) * 256 : -1;
        c2.idx = (yin1 && xin0) ? r1 + x0 * 256       : -1;
        c3.idx = (yin1 && xin1) ? r1 + (x0 + 1) * 256 : -1;
        c0.w = (1.f - ly) * (1.f - lx) * w;
        c1.w = (1.f - ly) * lx * w;
        c2.w = ly * (1.f - lx) * w;
        c3.w = ly * lx * w;
        s_iw[tid][0] = c0;
        s_iw[tid][1] = c1;
        s_iw[tid][2] = c2;
        s_iw[tid][3] = c3;
    }
    __syncthreads();

    const int head = tid >> 5;
    const int lane = tid & 31;
    const int g    = lane >> 3;   // corner group 0..3
    const int sub  = lane & 7;    // channel quad 0..7

    float4 a = make_float4(0.f, 0.f, 0.f, 0.f);
#pragma unroll
    for (int i = 0; i < 16; i++) {
        const IW p = s_iw[head * 16 + i][g];
        if (p.idx >= 0) {
            const float4 v = *reinterpret_cast<const float4*>(value + p.idx + (sub << 2));
            a.x = fmaf(p.w, v.x, a.x);
            a.y = fmaf(p.w, v.y, a.y);
            a.z = fmaf(p.w, v.z, a.z);
            a.w = fmaf(p.w, v.w, a.w);
        }
    }
    // reduce across the 4 corner groups (lanes differing in bits 3,4)
#pragma unroll
    for (int o = 8; o <= 16; o <<= 1) {
        a.x += __shfl_xor_sync(0xffffffffu, a.x, o);
        a.y += __shfl_xor_sync(0xffffffffu, a.y, o);
        a.z += __shfl_xor_sync(0xffffffffu, a.z, o);
        a.w += __shfl_xor_sync(0xffffffffu, a.w, o);
    }
    if (lane < 8)
        *reinterpret_cast<float4*>(acc + (size_t)row * 256 + head * 32 + (sub << 2)) = a;
}

// ---------------- launch ----------------
extern "C" void kernel_launch(void* const* d_in, const int* in_sizes, int n_in,
                              void* d_out, int out_size) {
    const float* query  = (const float*)d_in[0];
    const float* refpts = (const float*)d_in[1];
    // d_in[2]: spatial_shapes (unused — baked in as constants)
    const float* Wv   = (const float*)d_in[3];
    const float* bv   = (const float*)d_in[4];
    const float* Woff = (const float*)d_in[5];
    const float* boff = (const float*)d_in[6];
    const float* Wat  = (const float*)d_in[7];
    const float* bat  = (const float*)d_in[8];
    const float* Wout = (const float*)d_in[9];
    const float* bout = (const float*)d_in[10];
    float* out = (float*)d_out;

    float *p_value, *p_off, *p_attn, *p_acc;
    cudaGetSymbolAddress((void**)&p_value, g_value);
    cudaGetSymbolAddress((void**)&p_off,   g_off);
    cudaGetSymbolAddress((void**)&p_attn,  g_attn);
    cudaGetSymbolAddress((void**)&p_acc,   g_acc);

    const int M = M_TOT;
    const dim3 blk(256);
    const int gy = (M + TM - 1) / TM;   // 208

    // projections
    gemm_bias_kernel<<<dim3(EMBED / TN, gy), blk>>>(query, Wv,   bv,   nullptr, p_value, M, EMBED, EMBED);
    gemm_bias_kernel<<<dim3(256   / TN, gy), blk>>>(query, Woff, boff, nullptr, p_off,   M, 256,   EMBED);
    gemm_bias_kernel<<<dim3(128   / TN, gy), blk>>>(query, Wat,  bat,  nullptr, p_attn,  M, 128,   EMBED);

    // deformable sampling (+ fused softmax)
    msda_sample_kernel<<<M, HEADS * 32>>>(refpts, p_off, p_attn, p_value, p_acc);

    // output projection + bias + residual
    gemm_bias_kernel<<<dim3(EMBED / TN, gy), blk>>>(p_acc, Wout, bout, query, out, M, EMBED, EMBED);
}

// round 4
// speedup vs baseline: 1.3093x; 1.3093x over previous
#include <cuda_runtime.h>
#include <cuda_bf16.h>
#include <cstdint>

// ---------------- problem constants (compile-time) ----------------
#define NQ      13294          // 100*100 + 50*50 + 25*25 + 13*13
#define BS      2
#define M_TOT   (BS * NQ)      // 26588
#define EMBED   256
#define HEADS   8
#define DIM     32
#define LEVELS  4
#define POINTS  4
#define K3      768            // 3 * EMBED (split-bf16 expanded K)

__device__ __constant__ int c_Wl[LEVELS]    = {100, 50, 25, 13};
__device__ __constant__ int c_Hl[LEVELS]    = {100, 50, 25, 13};
__device__ __constant__ int c_start[LEVELS] = {0, 10000, 12500, 13125};

// ---------------- scratch (static device memory, no allocation) ----------------
__device__ float g_value[(size_t)M_TOT * EMBED];   // (b,q,heads,dim)
__device__ float g_off  [(size_t)M_TOT * 256];     // (b,q,heads,levels,points,2)
__device__ float g_attn [(size_t)M_TOT * 128];     // (b,q,heads,16) raw logits
__device__ float g_acc  [(size_t)M_TOT * EMBED];   // sampled output

// split-bf16 operands: A' = [Ah, Ah, Al] (M x 768), B' = [Bh; Bl; Bh] (768 x N)
__device__ __nv_bfloat16 g_A2q [(size_t)M_TOT * K3];
__device__ __nv_bfloat16 g_A2a [(size_t)M_TOT * K3];
__device__ __nv_bfloat16 g_B2v [(size_t)K3 * 256];
__device__ __nv_bfloat16 g_B2o [(size_t)K3 * 256];
__device__ __nv_bfloat16 g_B2a [(size_t)K3 * 128];
__device__ __nv_bfloat16 g_B2u [(size_t)K3 * 256];

// ---------------- split-precision prep kernels ----------------
__global__ void prep_act_kernel(const float* __restrict__ X,
                                __nv_bfloat16* __restrict__ A2, int M) {
    const int idx = blockIdx.x * blockDim.x + threadIdx.x;
    if (idx >= M * EMBED) return;
    const int row = idx >> 8;
    const int k   = idx & 255;
    const float v = X[idx];
    const __nv_bfloat16 hi = __float2bfloat16_rn(v);
    const __nv_bfloat16 lo = __float2bfloat16_rn(v - __bfloat162float(hi));
    const size_t b = (size_t)row * K3;
    A2[b + k]       = hi;
    A2[b + 256 + k] = hi;
    A2[b + 512 + k] = lo;
}

__global__ void prep_weight_kernel(const float* __restrict__ W,
                                   __nv_bfloat16* __restrict__ B2, int N) {
    const int idx = blockIdx.x * blockDim.x + threadIdx.x;
    if (idx >= EMBED * N) return;
    const int k = idx / N;
    const int n = idx - k * N;
    const float v = W[idx];
    const __nv_bfloat16 hi = __float2bfloat16_rn(v);
    const __nv_bfloat16 lo = __float2bfloat16_rn(v - __bfloat162float(hi));
    B2[(size_t)k * N + n]         = hi;
    B2[(size_t)(256 + k) * N + n] = lo;
    B2[(size_t)(512 + k) * N + n] = hi;
}

// ---------------- bf16 tensor-core GEMM ----------------
// C(MxN fp32) = A'(Mx768 bf16) @ B'(768xN bf16) + bias (+ resid)
// 128x128 tile, 256 threads = 8 warps (2m x 4n), warp tile 64x32,
// mma.sync.m16n8k16. Padded smem strides keep every ldmatrix phase
// on 8 distinct 16B bank groups (conflict-free).
#define GBM 128
#define GBN 128
#define GBK 16
#define AS_STRIDE 24    // 16 + 8 bf16
#define BS_STRIDE 136   // 128 + 8 bf16

__global__ void __launch_bounds__(256)
gemm_bf16_kernel(const __nv_bfloat16* __restrict__ A,
                 const __nv_bfloat16* __restrict__ B,
                 const float* __restrict__ bias,
                 const float* __restrict__ resid,
                 float* __restrict__ C,
                 int M, int N) {
    __shared__ __align__(16) __nv_bfloat16 As[2][GBM * AS_STRIDE];
    __shared__ __align__(16) __nv_bfloat16 Bs[2][GBK * BS_STRIDE];

    const int tid  = threadIdx.x;
    const int wid  = tid >> 5;
    const int lane = tid & 31;
    const int m_w  = wid >> 2;       // 0..1 -> * 64
    const int n_w  = wid & 3;        // 0..3 -> * 32
    const int m0   = blockIdx.y * GBM;
    const int n0   = blockIdx.x * GBN;

    // global-load mapping (one uint4 = 8 bf16 per thread per tile)
    const int a_row = tid >> 1;           // 0..127
    const int a_col = (tid & 1) << 3;     // 0 / 8
    const int b_row = tid >> 4;           // 0..15
    const int b_col = (tid & 15) << 3;    // 0..120

    const bool a_ok = (m0 + a_row) < M;
    const __nv_bfloat16* Ag = A + (size_t)(m0 + a_row) * K3 + a_col;
    const __nv_bfloat16* Bg = B + (size_t)b_row * N + n0 + b_col;

    float acc[4][4][4];
#pragma unroll
    for (int i = 0; i < 4; i++)
#pragma unroll
        for (int j = 0; j < 4; j++)
#pragma unroll
            for (int r = 0; r < 4; r++) acc[i][j][r] = 0.f;

    const uint4 zero4 = make_uint4(0u, 0u, 0u, 0u);
    uint4 ra = a_ok ? *reinterpret_cast<const uint4*>(Ag) : zero4;
    uint4 rb = *reinterpret_cast<const uint4*>(Bg);
    *reinterpret_cast<uint4*>(&As[0][a_row * AS_STRIDE + a_col]) = ra;
    *reinterpret_cast<uint4*>(&Bs[0][b_row * BS_STRIDE + b_col]) = rb;
    __syncthreads();

    const int NSTEP = K3 / GBK;   // 48
    for (int ks = 0; ks < NSTEP; ks++) {
        const int cur = ks & 1;
        if (ks + 1 < NSTEP) {     // register prefetch of next tile
            ra = a_ok ? *reinterpret_cast<const uint4*>(Ag + (ks + 1) * GBK) : zero4;
            rb = *reinterpret_cast<const uint4*>(Bg + (size_t)(ks + 1) * GBK * N);
        }

        const uint32_t smA = (uint32_t)__cvta_generic_to_shared(&As[cur][0]);
        const uint32_t smB = (uint32_t)__cvta_generic_to_shared(&Bs[cur][0]);

        uint32_t af[4][4];
#pragma unroll
        for (int mt = 0; mt < 4; mt++) {
            const uint32_t addr = smA +
                ((m_w * 64 + mt * 16 + (lane & 15)) * AS_STRIDE + ((lane >> 4) << 3)) * 2;
            asm volatile("ldmatrix.sync.aligned.m8n8.x4.shared.b16 {%0,%1,%2,%3}, [%4];"
                         : "=r"(af[mt][0]), "=r"(af[mt][1]), "=r"(af[mt][2]), "=r"(af[mt][3])
                         : "r"(addr));
        }
        uint32_t bf[2][4];
#pragma unroll
        for (int np = 0; np < 2; np++) {
            const uint32_t addr = smB +
                ((lane & 15) * BS_STRIDE + n_w * 32 + np * 16 + ((lane >> 4) << 3)) * 2;
            asm volatile("ldmatrix.sync.aligned.m8n8.x4.trans.shared.b16 {%0,%1,%2,%3}, [%4];"
                         : "=r"(bf[np][0]), "=r"(bf[np][1]), "=r"(bf[np][2]), "=r"(bf[np][3])
                         : "r"(addr));
        }

#pragma unroll
        for (int mt = 0; mt < 4; mt++)
#pragma unroll
            for (int nt = 0; nt < 4; nt++) {
                const uint32_t b0 = bf[nt >> 1][(nt & 1) * 2];
                const uint32_t b1 = bf[nt >> 1][(nt & 1) * 2 + 1];
                asm volatile(
                    "mma.sync.aligned.m16n8k16.row.col.f32.bf16.bf16.f32 "
                    "{%0,%1,%2,%3}, {%4,%5,%6,%7}, {%8,%9}, {%0,%1,%2,%3};"
                    : "+f"(acc[mt][nt][0]), "+f"(acc[mt][nt][1]),
                      "+f"(acc[mt][nt][2]), "+f"(acc[mt][nt][3])
                    : "r"(af[mt][0]), "r"(af[mt][1]), "r"(af[mt][2]), "r"(af[mt][3]),
                      "r"(b0), "r"(b1));
            }

        __syncthreads();
        if (ks + 1 < NSTEP) {
            const int nxt = cur ^ 1;
            *reinterpret_cast<uint4*>(&As[nxt][a_row * AS_STRIDE + a_col]) = ra;
            *reinterpret_cast<uint4*>(&Bs[nxt][b_row * BS_STRIDE + b_col]) = rb;
            __syncthreads();
        }
    }

    // epilogue: c0,c1 -> (row g, cols 2t,2t+1); c2,c3 -> row g+8
    const int g  = lane >> 2;
    const int t4 = lane & 3;
#pragma unroll
    for (int mt = 0; mt < 4; mt++) {
#pragma unroll
        for (int nt = 0; nt < 4; nt++) {
            const int gm = m0 + m_w * 64 + mt * 16 + g;
            const int gn = n0 + n_w * 32 + nt * 8 + t4 * 2;
            const float b0 = bias[gn], b1 = bias[gn + 1];
            if (gm < M) {
                float v0 = acc[mt][nt][0] + b0;
                float v1 = acc[mt][nt][1] + b1;
                if (resid) {
                    v0 += resid[(size_t)gm * N + gn];
                    v1 += resid[(size_t)gm * N + gn + 1];
                }
                C[(size_t)gm * N + gn]     = v0;
                C[(size_t)gm * N + gn + 1] = v1;
            }
            if (gm + 8 < M) {
                float v2 = acc[mt][nt][2] + b0;
                float v3 = acc[mt][nt][3] + b1;
                if (resid) {
                    v2 += resid[(size_t)(gm + 8) * N + gn];
                    v3 += resid[(size_t)(gm + 8) * N + gn + 1];
                }
                C[(size_t)(gm + 8) * N + gn]     = v2;
                C[(size_t)(gm + 8) * N + gn + 1] = v3;
            }
        }
    }
}

// ---------------- sampling kernel (unchanged from R3) ----------------
struct IW { int idx; float w; };

__global__ void msda_sample_kernel(const float* __restrict__ ref,
                                   const float* __restrict__ off,
                                   const float* __restrict__ logits,
                                   const float* __restrict__ value,
                                   float* __restrict__ acc) {
    __shared__ IW s_iw[128][4];   // [(head,point)][corner]

    const int row = blockIdx.x;
    const int tid = threadIdx.x;
    const int vbase = (row >= NQ) ? NQ : 0;   // b * NQ

    if (tid < 128) {
        const int head = tid >> 4;
        const int i    = tid & 15;     // (level,point)
        const int l    = i >> 2;
        const int Wl = c_Wl[l], Hl = c_Hl[l];

        float lg = __ldg(logits + (size_t)row * 128 + tid);
        float mx = lg;
#pragma unroll
        for (int o = 8; o >= 1; o >>= 1)
            mx = fmaxf(mx, __shfl_xor_sync(0xffffffffu, mx, o, 16));
        float e = __expf(lg - mx);
        float s = e;
#pragma unroll
        for (int o = 8; o >= 1; o >>= 1)
            s += __shfl_xor_sync(0xffffffffu, s, o, 16);
        const float w = e * __frcp_rn(s);

        const float rx = __ldg(ref + (size_t)row * 8 + 2 * l + 0) * (float)Wl - 0.5f;
        const float ry = __ldg(ref + (size_t)row * 8 + 2 * l + 1) * (float)Hl - 0.5f;
        const float2 o2 = *reinterpret_cast<const float2*>(off + (size_t)row * 256 + head * 32 + 2 * i);
        const float x = rx + o2.x;
        const float y = ry + o2.y;

        const float xf = floorf(x), yf = floorf(y);
        const int x0 = (int)xf, y0 = (int)yf;
        const float lx = x - xf, ly = y - yf;

        const bool yin0 = (y0 >= 0) & (y0 < Hl);
        const bool yin1 = (y0 + 1 >= 0) & (y0 + 1 < Hl);
        const bool xin0 = (x0 >= 0) & (x0 < Wl);
        const bool xin1 = (x0 + 1 >= 0) & (x0 + 1 < Wl);

        const int base = vbase + c_start[l];
        const int r0 = (base + y0 * Wl) * 256 + head * 32;
        const int r1 = r0 + Wl * 256;

        IW c0, c1, c2, c3;
        c0.idx = (yin0 && xin0) ? r0 + x0 * 256       : -1;
        c1.idx = (yin0 && xin1) ? r0 + (x0 + 1) * 256 : -1;
        c2.idx = (yin1 && xin0) ? r1 + x0 * 256       : -1;
        c3.idx = (yin1 && xin1) ? r1 + (x0 + 1) * 256 : -1;
        c0.w = (1.f - ly) * (1.f - lx) * w;
        c1.w = (1.f - ly) * lx * w;
        c2.w = ly * (1.f - lx) * w;
        c3.w = ly * lx * w;
        s_iw[tid][0] = c0;
        s_iw[tid][1] = c1;
        s_iw[tid][2] = c2;
        s_iw[tid][3] = c3;
    }
    __syncthreads();

    const int head = tid >> 5;
    const int lane = tid & 31;
    const int g    = lane >> 3;   // corner group 0..3
    const int sub  = lane & 7;    // channel quad 0..7

    float4 a = make_float4(0.f, 0.f, 0.f, 0.f);
#pragma unroll
    for (int i = 0; i < 16; i++) {
        const IW p = s_iw[head * 16 + i][g];
        if (p.idx >= 0) {
            const float4 v = *reinterpret_cast<const float4*>(value + p.idx + (sub << 2));
            a.x = fmaf(p.w, v.x, a.x);
            a.y = fmaf(p.w, v.y, a.y);
            a.z = fmaf(p.w, v.z, a.z);
            a.w = fmaf(p.w, v.w, a.w);
        }
    }
#pragma unroll
    for (int o = 8; o <= 16; o <<= 1) {
        a.x += __shfl_xor_sync(0xffffffffu, a.x, o);
        a.y += __shfl_xor_sync(0xffffffffu, a.y, o);
        a.z += __shfl_xor_sync(0xffffffffu, a.z, o);
        a.w += __shfl_xor_sync(0xffffffffu, a.w, o);
    }
    if (lane < 8)
        *reinterpret_cast<float4*>(acc + (size_t)row * 256 + head * 32 + (sub << 2)) = a;
}

// ---------------- launch ----------------
extern "C" void kernel_launch(void* const* d_in, const int* in_sizes, int n_in,
                              void* d_out, int out_size) {
    const float* query  = (const float*)d_in[0];
    const float* refpts = (const float*)d_in[1];
    // d_in[2]: spatial_shapes (unused — baked in as constants)
    const float* Wv   = (const float*)d_in[3];
    const float* bv   = (const float*)d_in[4];
    const float* Woff = (const float*)d_in[5];
    const float* boff = (const float*)d_in[6];
    const float* Wat  = (const float*)d_in[7];
    const float* bat  = (const float*)d_in[8];
    const float* Wout = (const float*)d_in[9];
    const float* bout = (const float*)d_in[10];
    float* out = (float*)d_out;

    float *p_value, *p_off, *p_attn, *p_acc;
    __nv_bfloat16 *p_A2q, *p_A2a, *p_B2v, *p_B2o, *p_B2a, *p_B2u;
    cudaGetSymbolAddress((void**)&p_value, g_value);
    cudaGetSymbolAddress((void**)&p_off,   g_off);
    cudaGetSymbolAddress((void**)&p_attn,  g_attn);
    cudaGetSymbolAddress((void**)&p_acc,   g_acc);
    cudaGetSymbolAddress((void**)&p_A2q,   g_A2q);
    cudaGetSymbolAddress((void**)&p_A2a,   g_A2a);
    cudaGetSymbolAddress((void**)&p_B2v,   g_B2v);
    cudaGetSymbolAddress((void**)&p_B2o,   g_B2o);
    cudaGetSymbolAddress((void**)&p_B2a,   g_B2a);
    cudaGetSymbolAddress((void**)&p_B2u,   g_B2u);

    const int M  = M_TOT;
    const int gy = (M + GBM - 1) / GBM;   // 208

    // split-precision preps
    prep_weight_kernel<<<(EMBED * 256 + 255) / 256, 256>>>(Wv,   p_B2v, 256);
    prep_weight_kernel<<<(EMBED * 256 + 255) / 256, 256>>>(Woff, p_B2o, 256);
    prep_weight_kernel<<<(EMBED * 128 + 255) / 256, 256>>>(Wat,  p_B2a, 128);
    prep_weight_kernel<<<(EMBED * 256 + 255) / 256, 256>>>(Wout, p_B2u, 256);
    prep_act_kernel<<<(M * EMBED + 255) / 256, 256>>>(query, p_A2q, M);

    // projections (tensor-core)
    gemm_bf16_kernel<<<dim3(2, gy), 256>>>(p_A2q, p_B2v, bv,   nullptr, p_value, M, 256);
    gemm_bf16_kernel<<<dim3(2, gy), 256>>>(p_A2q, p_B2o, boff, nullptr, p_off,   M, 256);
    gemm_bf16_kernel<<<dim3(1, gy), 256>>>(p_A2q, p_B2a, bat,  nullptr, p_attn,  M, 128);

    // deformable sampling (+ fused softmax)
    msda_sample_kernel<<<M, HEADS * 32>>>(refpts, p_off, p_attn, p_value, p_acc);

    // output projection + bias + residual
    prep_act_kernel<<<(M * EMBED + 255) / 256, 256>>>(p_acc, p_A2a, M);
    gemm_bf16_kernel<<<dim3(2, gy), 256>>>(p_A2a, p_B2u, bout, query, out, M, 256);
}

// round 6
// speedup vs baseline: 2.0562x; 1.5704x over previous
#include <cuda_runtime.h>
#include <cstdint>

// ---------------- problem constants ----------------
#define NQ      13294
#define BS      2
#define M_TOT   (BS * NQ)      // 26588
#define EMBED   256
#define HEADS   8
#define LEVELS  4
#define POINTS  4

__device__ __constant__ int c_Wl[LEVELS]    = {100, 50, 25, 13};
__device__ __constant__ int c_Hl[LEVELS]    = {100, 50, 25, 13};
__device__ __constant__ int c_start[LEVELS] = {0, 10000, 12500, 13125};

// ---------------- scratch ----------------
__device__ float g_value[(size_t)M_TOT * EMBED];
__device__ float g_off  [(size_t)M_TOT * 256];
__device__ float g_attn [(size_t)M_TOT * 128];
__device__ float g_acc  [(size_t)M_TOT * EMBED];

// ---------------- tf32 tensor-core GEMM ----------------
// C(MxN fp32) = A(Mx256 fp32) @ B(256xN fp32) + bias (+resid)
// mma.sync.m16n8k8.tf32, 128x128 tile, 256 threads = 8 warps (2m x 4n),
// warp tile 64x32. cp.async double-buffered. K fixed = 256.
#define GTK   16
#define NKS   (EMBED / GTK)    // 16
#define LDA   20               // smem floats per A row (perfect-permutation pad)
#define LDB   136              // smem floats per B row

__device__ __forceinline__ uint32_t smem_u32(const void* p) {
    return (uint32_t)__cvta_generic_to_shared(p);
}
__device__ __forceinline__ void cp_async16(uint32_t dst, const void* src, uint32_t sz) {
    asm volatile("cp.async.cg.shared.global [%0], [%1], 16, %2;"
                 :: "r"(dst), "l"(src), "r"(sz));
}
__device__ __forceinline__ uint32_t f2tf32(float f) {
    uint32_t r;
    asm("cvt.rna.tf32.f32 %0, %1;" : "=r"(r) : "f"(f));
    return r;
}

__global__ void __launch_bounds__(256)
gemm_tf32_kernel(const float* __restrict__ A,
                 const float* __restrict__ B,
                 const float* __restrict__ bias,
                 const float* __restrict__ resid,
                 float* __restrict__ C,
                 int M, int N) {
    __shared__ float sA[2][128 * LDA];   // 10240 B / stage
    __shared__ float sB[2][GTK * LDB];   //  8704 B / stage

    const int tid  = threadIdx.x;
    const int wid  = tid >> 5;
    const int lane = tid & 31;
    const int m_w  = (wid >> 2) * 64;
    const int n_w  = (wid & 3) * 32;
    const int m0   = blockIdx.y * 128;
    const int n0   = blockIdx.x * 128;

    const int grp = lane >> 2;   // 0..7
    const int tig = lane & 3;    // 0..3

    float acc[4][4][4];
#pragma unroll
    for (int i = 0; i < 4; i++)
#pragma unroll
        for (int j = 0; j < 4; j++)
#pragma unroll
            for (int r = 0; r < 4; r++) acc[i][j][r] = 0.f;

    // cp.async task mapping (2 tasks of 16B each per thread per tile)
    // A: 128 rows x 4 float4;  B: 16 rows x 32 float4
    const int aw_r0 = tid >> 2,          aw_c0 = tid & 3;         // task tid
    const int aw_r1 = (tid + 256) >> 2,  aw_c1 = tid & 3;         // task tid+256
    const int bw_r0 = tid >> 5,          bw_c0 = tid & 31;
    const int bw_r1 = (tid + 256) >> 5,  bw_c1 = tid & 31;

    auto load_stage = [&](int ks, int buf) {
        const int k0 = ks * GTK;
        {
            const int gm = m0 + aw_r0;
            cp_async16(smem_u32(&sA[buf][aw_r0 * LDA + aw_c0 * 4]),
                       A + (size_t)gm * EMBED + k0 + aw_c0 * 4, gm < M ? 16u : 0u);
        }
        {
            const int gm = m0 + aw_r1;
            cp_async16(smem_u32(&sA[buf][aw_r1 * LDA + aw_c1 * 4]),
                       A + (size_t)gm * EMBED + k0 + aw_c1 * 4, gm < M ? 16u : 0u);
        }
        cp_async16(smem_u32(&sB[buf][bw_r0 * LDB + bw_c0 * 4]),
                   B + (size_t)(k0 + bw_r0) * N + n0 + bw_c0 * 4, 16u);
        cp_async16(smem_u32(&sB[buf][bw_r1 * LDB + bw_c1 * 4]),
                   B + (size_t)(k0 + bw_r1) * N + n0 + bw_c1 * 4, 16u);
        asm volatile("cp.async.commit_group;" ::: "memory");
    };

    load_stage(0, 0);

    for (int ks = 0; ks < NKS; ks++) {
        const int buf = ks & 1;
        if (ks + 1 < NKS) {
            load_stage(ks + 1, buf ^ 1);
            asm volatile("cp.async.wait_group 1;" ::: "memory");
        } else {
            asm volatile("cp.async.wait_group 0;" ::: "memory");
        }
        __syncthreads();

#pragma unroll
        for (int sub = 0; sub < 2; sub++) {
            const int kb = sub * 8;
            uint32_t af[4][4];
#pragma unroll
            for (int mt = 0; mt < 4; mt++) {
                const int mrow = m_w + mt * 16 + grp;
                af[mt][0] = f2tf32(sA[buf][ mrow      * LDA + kb + tig]);
                af[mt][1] = f2tf32(sA[buf][(mrow + 8) * LDA + kb + tig]);
                af[mt][2] = f2tf32(sA[buf][ mrow      * LDA + kb + tig + 4]);
                af[mt][3] = f2tf32(sA[buf][(mrow + 8) * LDA + kb + tig + 4]);
            }
            uint32_t bf[4][2];
#pragma unroll
            for (int nt = 0; nt < 4; nt++) {
                const int ncol = n_w + nt * 8 + grp;
                bf[nt][0] = f2tf32(sB[buf][(kb + tig)     * LDB + ncol]);
                bf[nt][1] = f2tf32(sB[buf][(kb + tig + 4) * LDB + ncol]);
            }
#pragma unroll
            for (int mt = 0; mt < 4; mt++)
#pragma unroll
                for (int nt = 0; nt < 4; nt++) {
                    asm volatile(
                        "mma.sync.aligned.m16n8k8.row.col.f32.tf32.tf32.f32 "
                        "{%0,%1,%2,%3}, {%4,%5,%6,%7}, {%8,%9}, {%0,%1,%2,%3};"
                        : "+f"(acc[mt][nt][0]), "+f"(acc[mt][nt][1]),
                          "+f"(acc[mt][nt][2]), "+f"(acc[mt][nt][3])
                        : "r"(af[mt][0]), "r"(af[mt][1]), "r"(af[mt][2]), "r"(af[mt][3]),
                          "r"(bf[nt][0]), "r"(bf[nt][1]));
                }
        }
        __syncthreads();
    }

    // epilogue: c0,c1 -> (row grp, cols 2tig,2tig+1); c2,c3 -> row grp+8
#pragma unroll
    for (int mt = 0; mt < 4; mt++) {
#pragma unroll
        for (int nt = 0; nt < 4; nt++) {
            const int gm = m0 + m_w + mt * 16 + grp;
            const int gn = n0 + n_w + nt * 8 + tig * 2;
            const float b0 = bias[gn], b1 = bias[gn + 1];
            if (gm < M) {
                float v0 = acc[mt][nt][0] + b0;
                float v1 = acc[mt][nt][1] + b1;
                if (resid) {
                    v0 += resid[(size_t)gm * N + gn];
                    v1 += resid[(size_t)gm * N + gn + 1];
                }
                C[(size_t)gm * N + gn]     = v0;
                C[(size_t)gm * N + gn + 1] = v1;
            }
            if (gm + 8 < M) {
                float v2 = acc[mt][nt][2] + b0;
                float v3 = acc[mt][nt][3] + b1;
                if (resid) {
                    v2 += resid[(size_t)(gm + 8) * N + gn];
                    v3 += resid[(size_t)(gm + 8) * N + gn + 1];
                }
                C[(size_t)(gm + 8) * N + gn]     = v2;
                C[(size_t)(gm + 8) * N + gn + 1] = v3;
            }
        }
    }
}

// ---------------- sampling kernel (unchanged) ----------------
struct IW { int idx; float w; };

__global__ void msda_sample_kernel(const float* __restrict__ ref,
                                   const float* __restrict__ off,
                                   const float* __restrict__ logits,
                                   const float* __restrict__ value,
                                   float* __restrict__ acc) {
    __shared__ IW s_iw[128][4];

    const int row = blockIdx.x;
    const int tid = threadIdx.x;
    const int vbase = (row >= NQ) ? NQ : 0;

    if (tid < 128) {
        const int head = tid >> 4;
        const int i    = tid & 15;
        const int l    = i >> 2;
        const int Wl = c_Wl[l], Hl = c_Hl[l];

        float lg = __ldg(logits + (size_t)row * 128 + tid);
        float mx = lg;
#pragma unroll
        for (int o = 8; o >= 1; o >>= 1)
            mx = fmaxf(mx, __shfl_xor_sync(0xffffffffu, mx, o, 16));
        float e = __expf(lg - mx);
        float s = e;
#pragma unroll
        for (int o = 8; o >= 1; o >>= 1)
            s += __shfl_xor_sync(0xffffffffu, s, o, 16);
        const float w = e * __frcp_rn(s);

        const float rx = __ldg(ref + (size_t)row * 8 + 2 * l + 0) * (float)Wl - 0.5f;
        const float ry = __ldg(ref + (size_t)row * 8 + 2 * l + 1) * (float)Hl - 0.5f;
        const float2 o2 = *reinterpret_cast<const float2*>(off + (size_t)row * 256 + head * 32 + 2 * i);
        const float x = rx + o2.x;
        const float y = ry + o2.y;

        const float xf = floorf(x), yf = floorf(y);
        const int x0 = (int)xf, y0 = (int)yf;
        const float lx = x - xf, ly = y - yf;

        const bool yin0 = (y0 >= 0) & (y0 < Hl);
        const bool yin1 = (y0 + 1 >= 0) & (y0 + 1 < Hl);
        const bool xin0 = (x0 >= 0) & (x0 < Wl);
        const bool xin1 = (x0 + 1 >= 0) & (x0 + 1 < Wl);

        const int base = vbase + c_start[l];
        const int r0 = (base + y0 * Wl) * 256 + head * 32;
        const int r1 = r0 + Wl * 256;

        IW c0, c1, c2, c3;
        c0.idx = (yin0 && xin0) ? r0 + x0 * 256       : -1;
        c1.idx = (yin0 && xin1) ? r0 + (x0 + 1) * 256 : -1;
        c2.idx = (yin1 && xin0) ? r1 + x0 * 256       : -1;
        c3.idx = (yin1 && xin1) ? r1 + (x0 + 1) * 256 : -1;
        c0.w = (1.f - ly) * (1.f - lx) * w;
        c1.w = (1.f - ly) * lx * w;
        c2.w = ly * (1.f - lx) * w;
        c3.w = ly * lx * w;
        s_iw[tid][0] = c0;
        s_iw[tid][1] = c1;
        s_iw[tid][2] = c2;
        s_iw[tid][3] = c3;
    }
    __syncthreads();

    const int head = tid >> 5;
    const int lane = tid & 31;
    const int g    = lane >> 3;
    const int sub  = lane & 7;

    float4 a = make_float4(0.f, 0.f, 0.f, 0.f);
#pragma unroll
    for (int i = 0; i < 16; i++) {
        const IW p = s_iw[head * 16 + i][g];
        if (p.idx >= 0) {
            const float4 v = *reinterpret_cast<const float4*>(value + p.idx + (sub << 2));
            a.x = fmaf(p.w, v.x, a.x);
            a.y = fmaf(p.w, v.y, a.y);
            a.z = fmaf(p.w, v.z, a.z);
            a.w = fmaf(p.w, v.w, a.w);
        }
    }
#pragma unroll
    for (int o = 8; o <= 16; o <<= 1) {
        a.x += __shfl_xor_sync(0xffffffffu, a.x, o);
        a.y += __shfl_xor_sync(0xffffffffu, a.y, o);
        a.z += __shfl_xor_sync(0xffffffffu, a.z, o);
        a.w += __shfl_xor_sync(0xffffffffu, a.w, o);
    }
    if (lane < 8)
        *reinterpret_cast<float4*>(acc + (size_t)row * 256 + head * 32 + (sub << 2)) = a;
}

// ---------------- launch ----------------
extern "C" void kernel_launch(void* const* d_in, const int* in_sizes, int n_in,
                              void* d_out, int out_size) {
    const float* query  = (const float*)d_in[0];
    const float* refpts = (const float*)d_in[1];
    const float* Wv   = (const float*)d_in[3];
    const float* bv   = (const float*)d_in[4];
    const float* Woff = (const float*)d_in[5];
    const float* boff = (const float*)d_in[6];
    const float* Wat  = (const float*)d_in[7];
    const float* bat  = (const float*)d_in[8];
    const float* Wout = (const float*)d_in[9];
    const float* bout = (const float*)d_in[10];
    float* out = (float*)d_out;

    float *p_value, *p_off, *p_attn, *p_acc;
    cudaGetSymbolAddress((void**)&p_value, g_value);
    cudaGetSymbolAddress((void**)&p_off,   g_off);
    cudaGetSymbolAddress((void**)&p_attn,  g_attn);
    cudaGetSymbolAddress((void**)&p_acc,   g_acc);

    const int M  = M_TOT;
    const int gy = (M + 127) / 128;   // 208

    // projections (tf32 tensor-core, operands used directly — no preps)
    gemm_tf32_kernel<<<dim3(2, gy), 256>>>(query, Wv,   bv,   nullptr, p_value, M, 256);
    gemm_tf32_kernel<<<dim3(2, gy), 256>>>(query, Woff, boff, nullptr, p_off,   M, 256);
    gemm_tf32_kernel<<<dim3(1, gy), 256>>>(query, Wat,  bat,  nullptr, p_attn,  M, 128);

    // deformable sampling (+ fused softmax)
    msda_sample_kernel<<<M, HEADS * 32>>>(refpts, p_off, p_attn, p_value, p_acc);

    // output projection + bias + residual
    gemm_tf32_kernel<<<dim3(2, gy), 256>>>(p_acc, Wout, bout, query, out, M, 256);
}

// round 7
// speedup vs baseline: 2.0731x; 1.0082x over previous
#include <cuda_runtime.h>
#include <cstdint>

// ---------------- problem constants ----------------
#define NQ      13294
#define BS      2
#define M_TOT   (BS * NQ)      // 26588
#define EMBED   256
#define HEADS   8
#define LEVELS  4
#define POINTS  4
#define NPROJ   640            // 256 (value) + 256 (off) + 128 (attn)

__device__ __constant__ int c_Wl[LEVELS]    = {100, 50, 25, 13};
__device__ __constant__ int c_Hl[LEVELS]    = {100, 50, 25, 13};
__device__ __constant__ int c_start[LEVELS] = {0, 10000, 12500, 13125};

// ---------------- scratch ----------------
__device__ float g_proj[(size_t)M_TOT * NPROJ];  // [value(256) | off(256) | attn(128)]
__device__ float g_acc [(size_t)M_TOT * EMBED];
__device__ float g_Wcat[(size_t)EMBED * NPROJ];
__device__ float g_bcat[NPROJ];

// ---------------- pack kernel: concat weights + biases ----------------
__global__ void pack_kernel(const float* __restrict__ Wv, const float* __restrict__ Woff,
                            const float* __restrict__ Wat, const float* __restrict__ bv,
                            const float* __restrict__ boff, const float* __restrict__ bat,
                            float* __restrict__ Wcat, float* __restrict__ bcat) {
    const int idx = blockIdx.x * blockDim.x + threadIdx.x;
    if (idx < EMBED * NPROJ) {
        const int k = idx / NPROJ;
        const int n = idx - k * NPROJ;
        float v;
        if (n < 256)      v = Wv  [k * 256 + n];
        else if (n < 512) v = Woff[k * 256 + (n - 256)];
        else              v = Wat [k * 128 + (n - 512)];
        Wcat[idx] = v;
    }
    if (idx < NPROJ) {
        float b;
        if (idx < 256)      b = bv  [idx];
        else if (idx < 512) b = boff[idx - 256];
        else                b = bat [idx - 512];
        bcat[idx] = b;
    }
}

// ---------------- tf32 tensor-core GEMM, 4-stage cp.async ----------------
// C(MxN) = A(MxK=256, lda) @ B(256xN, ldb) + bias (+resid, stride ldc)
#define GTK     16
#define NKS     (EMBED / GTK)    // 16
#define LDA     20               // smem floats per A row (perfect-permutation pad)
#define LDB     136              // smem floats per B row
#define STAGES  4
#define A_STG   (128 * LDA)      // floats per A stage
#define B_STG   (GTK * LDB)      // floats per B stage
#define SMEM_GEMM ((STAGES * (A_STG + B_STG)) * 4)   // 75776 bytes

__device__ __forceinline__ uint32_t smem_u32(const void* p) {
    return (uint32_t)__cvta_generic_to_shared(p);
}
__device__ __forceinline__ void cp_async16(uint32_t dst, const void* src, uint32_t sz) {
    asm volatile("cp.async.cg.shared.global [%0], [%1], 16, %2;"
                 :: "r"(dst), "l"(src), "r"(sz));
}
__device__ __forceinline__ uint32_t f2tf32(float f) {
    uint32_t r;
    asm("cvt.rna.tf32.f32 %0, %1;" : "=r"(r) : "f"(f));
    return r;
}

__global__ void __launch_bounds__(256, 2)
gemm_tf32_kernel(const float* __restrict__ A, int lda,
                 const float* __restrict__ B, int ldb,
                 const float* __restrict__ bias,
                 const float* __restrict__ resid,
                 float* __restrict__ C, int ldc,
                 int M) {
    extern __shared__ __align__(16) float smem[];
    float* sA = smem;                       // [STAGES][A_STG]
    float* sB = smem + STAGES * A_STG;      // [STAGES][B_STG]

    const int tid  = threadIdx.x;
    const int wid  = tid >> 5;
    const int lane = tid & 31;
    const int m_w  = (wid >> 2) * 64;
    const int n_w  = (wid & 3) * 32;
    const int m0   = blockIdx.y * 128;
    const int n0   = blockIdx.x * 128;

    const int grp = lane >> 2;   // 0..7
    const int tig = lane & 3;    // 0..3

    float acc[4][4][4];
#pragma unroll
    for (int i = 0; i < 4; i++)
#pragma unroll
        for (int j = 0; j < 4; j++)
#pragma unroll
            for (int r = 0; r < 4; r++) acc[i][j][r] = 0.f;

    // cp.async task mapping (2x 16B per thread per stage for A and B)
    const int aw_r0 = tid >> 2,         aw_c = tid & 3;
    const int aw_r1 = (tid + 256) >> 2;
    const int bw_r0 = tid >> 5,         bw_c = tid & 31;
    const int bw_r1 = (tid + 256) >> 5;

    auto load_stage = [&](int ks) {
        const int buf = ks % STAGES;
        const int k0  = ks * GTK;
        float* dA = sA + buf * A_STG;
        float* dB = sB + buf * B_STG;
        {
            const int gm = m0 + aw_r0;
            cp_async16(smem_u32(&dA[aw_r0 * LDA + aw_c * 4]),
                       A + (size_t)gm * lda + k0 + aw_c * 4, gm < M ? 16u : 0u);
        }
        {
            const int gm = m0 + aw_r1;
            cp_async16(smem_u32(&dA[aw_r1 * LDA + aw_c * 4]),
                       A + (size_t)gm * lda + k0 + aw_c * 4, gm < M ? 16u : 0u);
        }
        cp_async16(smem_u32(&dB[bw_r0 * LDB + bw_c * 4]),
                   B + (size_t)(k0 + bw_r0) * ldb + n0 + bw_c * 4, 16u);
        cp_async16(smem_u32(&dB[bw_r1 * LDB + bw_c * 4]),
                   B + (size_t)(k0 + bw_r1) * ldb + n0 + bw_c * 4, 16u);
    };

    // prologue: stages 0..STAGES-2 in flight
#pragma unroll
    for (int s = 0; s < STAGES - 1; s++) {
        load_stage(s);
        asm volatile("cp.async.commit_group;" ::: "memory");
    }

    for (int ks = 0; ks < NKS; ks++) {
        asm volatile("cp.async.wait_group %0;" :: "n"(STAGES - 2) : "memory");
        __syncthreads();

        if (ks + STAGES - 1 < NKS) load_stage(ks + STAGES - 1);
        asm volatile("cp.async.commit_group;" ::: "memory");   // may be empty

        const float* cA = sA + (ks % STAGES) * A_STG;
        const float* cB = sB + (ks % STAGES) * B_STG;

#pragma unroll
        for (int sub = 0; sub < 2; sub++) {
            const int kb = sub * 8;
            uint32_t af[4][4];
#pragma unroll
            for (int mt = 0; mt < 4; mt++) {
                const int mrow = m_w + mt * 16 + grp;
                af[mt][0] = f2tf32(cA[ mrow      * LDA + kb + tig]);
                af[mt][1] = f2tf32(cA[(mrow + 8) * LDA + kb + tig]);
                af[mt][2] = f2tf32(cA[ mrow      * LDA + kb + tig + 4]);
                af[mt][3] = f2tf32(cA[(mrow + 8) * LDA + kb + tig + 4]);
            }
            uint32_t bf[4][2];
#pragma unroll
            for (int nt = 0; nt < 4; nt++) {
                const int ncol = n_w + nt * 8 + grp;
                bf[nt][0] = f2tf32(cB[(kb + tig)     * LDB + ncol]);
                bf[nt][1] = f2tf32(cB[(kb + tig + 4) * LDB + ncol]);
            }
#pragma unroll
            for (int mt = 0; mt < 4; mt++)
#pragma unroll
                for (int nt = 0; nt < 4; nt++) {
                    asm volatile(
                        "mma.sync.aligned.m16n8k8.row.col.f32.tf32.tf32.f32 "
                        "{%0,%1,%2,%3}, {%4,%5,%6,%7}, {%8,%9}, {%0,%1,%2,%3};"
                        : "+f"(acc[mt][nt][0]), "+f"(acc[mt][nt][1]),
                          "+f"(acc[mt][nt][2]), "+f"(acc[mt][nt][3])
                        : "r"(af[mt][0]), "r"(af[mt][1]), "r"(af[mt][2]), "r"(af[mt][3]),
                          "r"(bf[nt][0]), "r"(bf[nt][1]));
                }
        }
        __syncthreads();
    }

    // epilogue
#pragma unroll
    for (int mt = 0; mt < 4; mt++) {
#pragma unroll
        for (int nt = 0; nt < 4; nt++) {
            const int gm = m0 + m_w + mt * 16 + grp;
            const int gn = n0 + n_w + nt * 8 + tig * 2;
            const float b0 = bias[gn], b1 = bias[gn + 1];
            if (gm < M) {
                float v0 = acc[mt][nt][0] + b0;
                float v1 = acc[mt][nt][1] + b1;
                if (resid) {
                    v0 += resid[(size_t)gm * ldc + gn];
                    v1 += resid[(size_t)gm * ldc + gn + 1];
                }
                C[(size_t)gm * ldc + gn]     = v0;
                C[(size_t)gm * ldc + gn + 1] = v1;
            }
            if (gm + 8 < M) {
                float v2 = acc[mt][nt][2] + b0;
                float v3 = acc[mt][nt][3] + b1;
                if (resid) {
                    v2 += resid[(size_t)(gm + 8) * ldc + gn];
                    v3 += resid[(size_t)(gm + 8) * ldc + gn + 1];
                }
                C[(size_t)(gm + 8) * ldc + gn]     = v2;
                C[(size_t)(gm + 8) * ldc + gn + 1] = v3;
            }
        }
    }
}

// ---------------- sampling kernel ----------------
// Reads value/off/logits from fused g_proj (row stride 640):
//   value[pix][head][ch] = proj[pix*640 + head*32 + ch]   (128B head-rows, aligned)
//   off   at col 256, logits at col 512.
struct IW { int idx; float w; };

__global__ void msda_sample_kernel(const float* __restrict__ ref,
                                   const float* __restrict__ proj,
                                   float* __restrict__ acc) {
    __shared__ IW s_iw[128][4];

    const int row = blockIdx.x;
    const int tid = threadIdx.x;
    const int vbase = (row >= NQ) ? NQ : 0;

    if (tid < 128) {
        const int head = tid >> 4;
        const int i    = tid & 15;
        const int l    = i >> 2;
        const int Wl = c_Wl[l], Hl = c_Hl[l];

        float lg = __ldg(proj + (size_t)row * NPROJ + 512 + tid);
        float mx = lg;
#pragma unroll
        for (int o = 8; o >= 1; o >>= 1)
            mx = fmaxf(mx, __shfl_xor_sync(0xffffffffu, mx, o, 16));
        float e = __expf(lg - mx);
        float s = e;
#pragma unroll
        for (int o = 8; o >= 1; o >>= 1)
            s += __shfl_xor_sync(0xffffffffu, s, o, 16);
        const float w = e * __frcp_rn(s);

        const float rx = __ldg(ref + (size_t)row * 8 + 2 * l + 0) * (float)Wl - 0.5f;
        const float ry = __ldg(ref + (size_t)row * 8 + 2 * l + 1) * (float)Hl - 0.5f;
        const float2 o2 = *reinterpret_cast<const float2*>(
            proj + (size_t)row * NPROJ + 256 + head * 32 + 2 * i);
        const float x = rx + o2.x;
        const float y = ry + o2.y;

        const float xf = floorf(x), yf = floorf(y);
        const int x0 = (int)xf, y0 = (int)yf;
        const float lx = x - xf, ly = y - yf;

        const bool yin0 = (y0 >= 0) & (y0 < Hl);
        const bool yin1 = (y0 + 1 >= 0) & (y0 + 1 < Hl);
        const bool xin0 = (x0 >= 0) & (x0 < Wl);
        const bool xin1 = (x0 + 1 >= 0) & (x0 + 1 < Wl);

        const int base = vbase + c_start[l];
        const int r0 = (base + y0 * Wl) * NPROJ + head * 32;
        const int r1 = r0 + Wl * NPROJ;

        IW c0, c1, c2, c3;
        c0.idx = (yin0 && xin0) ? r0 + x0 * NPROJ       : -1;
        c1.idx = (yin0 && xin1) ? r0 + (x0 + 1) * NPROJ : -1;
        c2.idx = (yin1 && xin0) ? r1 + x0 * NPROJ       : -1;
        c3.idx = (yin1 && xin1) ? r1 + (x0 + 1) * NPROJ : -1;
        c0.w = (1.f - ly) * (1.f - lx) * w;
        c1.w = (1.f - ly) * lx * w;
        c2.w = ly * (1.f - lx) * w;
        c3.w = ly * lx * w;
        s_iw[tid][0] = c0;
        s_iw[tid][1] = c1;
        s_iw[tid][2] = c2;
        s_iw[tid][3] = c3;
    }
    __syncthreads();

    const int head = tid >> 5;
    const int lane = tid & 31;
    const int g    = lane >> 3;   // corner group
    const int sub  = lane & 7;    // channel quad

    // preload all 16 (idx,w) pairs -> registers (MLP-friendly)
    int   ji[16];
    float wi[16];
#pragma unroll
    for (int i = 0; i < 16; i++) {
        const IW p = s_iw[head * 16 + i][g];
        ji[i] = p.idx;
        wi[i] = p.w;
    }

    float4 a = make_float4(0.f, 0.f, 0.f, 0.f);
#pragma unroll
    for (int b = 0; b < 2; b++) {
        float4 v[8];
#pragma unroll
        for (int j = 0; j < 8; j++) {
            const int id = ji[b * 8 + j];
            v[j] = (id >= 0)
                 ? *reinterpret_cast<const float4*>(proj + id + (sub << 2))
                 : make_float4(0.f, 0.f, 0.f, 0.f);
        }
#pragma unroll
        for (int j = 0; j < 8; j++) {
            const float w = wi[b * 8 + j];
            a.x = fmaf(w, v[j].x, a.x);
            a.y = fmaf(w, v[j].y, a.y);
            a.z = fmaf(w, v[j].z, a.z);
            a.w = fmaf(w, v[j].w, a.w);
        }
    }
#pragma unroll
    for (int o = 8; o <= 16; o <<= 1) {
        a.x += __shfl_xor_sync(0xffffffffu, a.x, o);
        a.y += __shfl_xor_sync(0xffffffffu, a.y, o);
        a.z += __shfl_xor_sync(0xffffffffu, a.z, o);
        a.w += __shfl_xor_sync(0xffffffffu, a.w, o);
    }
    if (lane < 8)
        *reinterpret_cast<float4*>(acc + (size_t)row * 256 + head * 32 + (sub << 2)) = a;
}

// ---------------- launch ----------------
extern "C" void kernel_launch(void* const* d_in, const int* in_sizes, int n_in,
                              void* d_out, int out_size) {
    const float* query  = (const float*)d_in[0];
    const float* refpts = (const float*)d_in[1];
    const float* Wv   = (const float*)d_in[3];
    const float* bv   = (const float*)d_in[4];
    const float* Woff = (const float*)d_in[5];
    const float* boff = (const float*)d_in[6];
    const float* Wat  = (const float*)d_in[7];
    const float* bat  = (const float*)d_in[8];
    const float* Wout = (const float*)d_in[9];
    const float* bout = (const float*)d_in[10];
    float* out = (float*)d_out;

    float *p_proj, *p_acc, *p_Wcat, *p_bcat;
    cudaGetSymbolAddress((void**)&p_proj, g_proj);
    cudaGetSymbolAddress((void**)&p_acc,  g_acc);
    cudaGetSymbolAddress((void**)&p_Wcat, g_Wcat);
    cudaGetSymbolAddress((void**)&p_bcat, g_bcat);

    cudaFuncSetAttribute(gemm_tf32_kernel,
                         cudaFuncAttributeMaxDynamicSharedMemorySize, SMEM_GEMM);

    const int M  = M_TOT;
    const int gy = (M + 127) / 128;   // 208

    // pack concatenated projection weights + biases
    pack_kernel<<<(EMBED * NPROJ + 255) / 256, 256>>>(Wv, Woff, Wat, bv, boff, bat,
                                                      p_Wcat, p_bcat);

    // fused projection GEMM: M x 640
    gemm_tf32_kernel<<<dim3(NPROJ / 128, gy), 256, SMEM_GEMM>>>(
        query, EMBED, p_Wcat, NPROJ, p_bcat, nullptr, p_proj, NPROJ, M);

    // deformable sampling (+ fused softmax)
    msda_sample_kernel<<<M, HEADS * 32>>>(refpts, p_proj, p_acc);

    // output projection + bias + residual
    gemm_tf32_kernel<<<dim3(2, gy), 256, SMEM_GEMM>>>(
        p_acc, EMBED, Wout, EMBED, bout, query, out, EMBED, M);
}

// round 8
// speedup vs baseline: 2.0872x; 1.0068x over previous
#include <cuda_runtime.h>
#include <cstdint>

// ---------------- problem constants ----------------
#define NQ      13294
#define BS      2
#define M_TOT   (BS * NQ)      // 26588
#define EMBED   256
#define HEADS   8
#define LEVELS  4
#define POINTS  4
#define NPROJ   640            // 256 (value) + 256 (off) + 128 (attn)

__device__ __constant__ int c_Wl[LEVELS]    = {100, 50, 25, 13};
__device__ __constant__ int c_Hl[LEVELS]    = {100, 50, 25, 13};
__device__ __constant__ int c_start[LEVELS] = {0, 10000, 12500, 13125};

// ---------------- scratch ----------------
__device__ float g_proj[(size_t)M_TOT * NPROJ];  // [value(256) | off(256) | attn(128)]
__device__ float g_acc [(size_t)M_TOT * EMBED];
__device__ float g_Wcat[(size_t)EMBED * NPROJ];
__device__ float g_bcat[NPROJ];

// ---------------- pack kernel ----------------
__global__ void pack_kernel(const float* __restrict__ Wv, const float* __restrict__ Woff,
                            const float* __restrict__ Wat, const float* __restrict__ bv,
                            const float* __restrict__ boff, const float* __restrict__ bat,
                            float* __restrict__ Wcat, float* __restrict__ bcat) {
    const int idx = blockIdx.x * blockDim.x + threadIdx.x;
    if (idx < EMBED * NPROJ) {
        const int k = idx / NPROJ;
        const int n = idx - k * NPROJ;
        float v;
        if (n < 256)      v = Wv  [k * 256 + n];
        else if (n < 512) v = Woff[k * 256 + (n - 256)];
        else              v = Wat [k * 128 + (n - 512)];
        Wcat[idx] = v;
    }
    if (idx < NPROJ) {
        float b;
        if (idx < 256)      b = bv  [idx];
        else if (idx < 512) b = boff[idx - 256];
        else                b = bat [idx - 512];
        bcat[idx] = b;
    }
}

// ---------------- tf32 tensor-core GEMM, 4-stage cp.async ----------------
#define GTK     16
#define NKS     (EMBED / GTK)    // 16
#define LDA     20
#define LDB     136
#define STAGES  4
#define A_STG   (128 * LDA)
#define B_STG   (GTK * LDB)
#define SMEM_GEMM ((STAGES * (A_STG + B_STG)) * 4)   // 75776 bytes

__device__ __forceinline__ uint32_t smem_u32(const void* p) {
    return (uint32_t)__cvta_generic_to_shared(p);
}
__device__ __forceinline__ void cp_async16(uint32_t dst, const void* src, uint32_t sz) {
    asm volatile("cp.async.cg.shared.global [%0], [%1], 16, %2;"
                 :: "r"(dst), "l"(src), "r"(sz));
}
__device__ __forceinline__ uint32_t f2tf32(float f) {
    uint32_t r;
    asm("cvt.rna.tf32.f32 %0, %1;" : "=r"(r) : "f"(f));
    return r;
}

__global__ void __launch_bounds__(256)
gemm_tf32_kernel(const float* __restrict__ A, int lda,
                 const float* __restrict__ B, int ldb,
                 const float* __restrict__ bias,
                 const float* __restrict__ resid,
                 float* __restrict__ C, int ldc,
                 int M) {
    extern __shared__ __align__(16) float smem[];
    float* sA = smem;
    float* sB = smem + STAGES * A_STG;

    const int tid  = threadIdx.x;
    const int wid  = tid >> 5;
    const int lane = tid & 31;
    const int m_w  = (wid >> 2) * 64;
    const int n_w  = (wid & 3) * 32;
    const int m0   = blockIdx.y * 128;
    const int n0   = blockIdx.x * 128;

    const int grp = lane >> 2;
    const int tig = lane & 3;

    float acc[4][4][4];
#pragma unroll
    for (int i = 0; i < 4; i++)
#pragma unroll
        for (int j = 0; j < 4; j++)
#pragma unroll
            for (int r = 0; r < 4; r++) acc[i][j][r] = 0.f;

    const int aw_r0 = tid >> 2,         aw_c = tid & 3;
    const int aw_r1 = (tid + 256) >> 2;
    const int bw_r0 = tid >> 5,         bw_c = tid & 31;
    const int bw_r1 = (tid + 256) >> 5;

    auto load_stage = [&](int ks) {
        const int buf = ks % STAGES;
        const int k0  = ks * GTK;
        float* dA = sA + buf * A_STG;
        float* dB = sB + buf * B_STG;
        {
            const int gm = m0 + aw_r0;
            cp_async16(smem_u32(&dA[aw_r0 * LDA + aw_c * 4]),
                       A + (size_t)gm * lda + k0 + aw_c * 4, gm < M ? 16u : 0u);
        }
        {
            const int gm = m0 + aw_r1;
            cp_async16(smem_u32(&dA[aw_r1 * LDA + aw_c * 4]),
                       A + (size_t)gm * lda + k0 + aw_c * 4, gm < M ? 16u : 0u);
        }
        cp_async16(smem_u32(&dB[bw_r0 * LDB + bw_c * 4]),
                   B + (size_t)(k0 + bw_r0) * ldb + n0 + bw_c * 4, 16u);
        cp_async16(smem_u32(&dB[bw_r1 * LDB + bw_c * 4]),
                   B + (size_t)(k0 + bw_r1) * ldb + n0 + bw_c * 4, 16u);
    };

#pragma unroll
    for (int s = 0; s < STAGES - 1; s++) {
        load_stage(s);
        asm volatile("cp.async.commit_group;" ::: "memory");
    }

    // fragment load helper: fills af/bf for a given k8 sub-block
    auto load_frags = [&](const float* cA, const float* cB, int kb,
                          uint32_t af[4][4], uint32_t bf[4][2]) {
#pragma unroll
        for (int mt = 0; mt < 4; mt++) {
            const int mrow = m_w + mt * 16 + grp;
            af[mt][0] = f2tf32(cA[ mrow      * LDA + kb + tig]);
            af[mt][1] = f2tf32(cA[(mrow + 8) * LDA + kb + tig]);
            af[mt][2] = f2tf32(cA[ mrow      * LDA + kb + tig + 4]);
            af[mt][3] = f2tf32(cA[(mrow + 8) * LDA + kb + tig + 4]);
        }
#pragma unroll
        for (int nt = 0; nt < 4; nt++) {
            const int ncol = n_w + nt * 8 + grp;
            bf[nt][0] = f2tf32(cB[(kb + tig)     * LDB + ncol]);
            bf[nt][1] = f2tf32(cB[(kb + tig + 4) * LDB + ncol]);
        }
    };
    auto do_mma = [&](uint32_t af[4][4], uint32_t bf[4][2]) {
#pragma unroll
        for (int mt = 0; mt < 4; mt++)
#pragma unroll
            for (int nt = 0; nt < 4; nt++) {
                asm volatile(
                    "mma.sync.aligned.m16n8k8.row.col.f32.tf32.tf32.f32 "
                    "{%0,%1,%2,%3}, {%4,%5,%6,%7}, {%8,%9}, {%0,%1,%2,%3};"
                    : "+f"(acc[mt][nt][0]), "+f"(acc[mt][nt][1]),
                      "+f"(acc[mt][nt][2]), "+f"(acc[mt][nt][3])
                    : "r"(af[mt][0]), "r"(af[mt][1]), "r"(af[mt][2]), "r"(af[mt][3]),
                      "r"(bf[nt][0]), "r"(bf[nt][1]));
            }
    };

    uint32_t afA[4][4], bfA[4][2];   // double-buffered fragments
    uint32_t afB[4][4], bfB[4][2];

    for (int ks = 0; ks < NKS; ks++) {
        asm volatile("cp.async.wait_group %0;" :: "n"(STAGES - 2) : "memory");
        __syncthreads();

        if (ks + STAGES - 1 < NKS) load_stage(ks + STAGES - 1);
        asm volatile("cp.async.commit_group;" ::: "memory");

        const float* cA = sA + (ks % STAGES) * A_STG;
        const float* cB = sB + (ks % STAGES) * B_STG;

        load_frags(cA, cB, 0, afA, bfA);      // sub 0
        load_frags(cA, cB, 8, afB, bfB);      // prefetch sub 1
        do_mma(afA, bfA);                      // compute sub 0 (LDS of sub1 in flight)
        do_mma(afB, bfB);                      // compute sub 1
        __syncthreads();
    }

    // epilogue
#pragma unroll
    for (int mt = 0; mt < 4; mt++) {
#pragma unroll
        for (int nt = 0; nt < 4; nt++) {
            const int gm = m0 + m_w + mt * 16 + grp;
            const int gn = n0 + n_w + nt * 8 + tig * 2;
            const float b0 = bias[gn], b1 = bias[gn + 1];
            if (gm < M) {
                float v0 = acc[mt][nt][0] + b0;
                float v1 = acc[mt][nt][1] + b1;
                if (resid) {
                    v0 += resid[(size_t)gm * ldc + gn];
                    v1 += resid[(size_t)gm * ldc + gn + 1];
                }
                C[(size_t)gm * ldc + gn]     = v0;
                C[(size_t)gm * ldc + gn + 1] = v1;
            }
            if (gm + 8 < M) {
                float v2 = acc[mt][nt][2] + b0;
                float v3 = acc[mt][nt][3] + b1;
                if (resid) {
                    v2 += resid[(size_t)(gm + 8) * ldc + gn];
                    v3 += resid[(size_t)(gm + 8) * ldc + gn + 1];
                }
                C[(size_t)(gm + 8) * ldc + gn]     = v2;
                C[(size_t)(gm + 8) * ldc + gn + 1] = v3;
            }
        }
    }
}

// ---------------- sampling kernel (unchanged from R7) ----------------
struct IW { int idx; float w; };

__global__ void msda_sample_kernel(const float* __restrict__ ref,
                                   const float* __restrict__ proj,
                                   float* __restrict__ acc) {
    __shared__ IW s_iw[128][4];

    const int row = blockIdx.x;
    const int tid = threadIdx.x;
    const int vbase = (row >= NQ) ? NQ : 0;

    if (tid < 128) {
        const int head = tid >> 4;
        const int i    = tid & 15;
        const int l    = i >> 2;
        const int Wl = c_Wl[l], Hl = c_Hl[l];

        float lg = __ldg(proj + (size_t)row * NPROJ + 512 + tid);
        float mx = lg;
#pragma unroll
        for (int o = 8; o >= 1; o >>= 1)
            mx = fmaxf(mx, __shfl_xor_sync(0xffffffffu, mx, o, 16));
        float e = __expf(lg - mx);
        float s = e;
#pragma unroll
        for (int o = 8; o >= 1; o >>= 1)
            s += __shfl_xor_sync(0xffffffffu, s, o, 16);
        const float w = e * __frcp_rn(s);

        const float rx = __ldg(ref + (size_t)row * 8 + 2 * l + 0) * (float)Wl - 0.5f;
        const float ry = __ldg(ref + (size_t)row * 8 + 2 * l + 1) * (float)Hl - 0.5f;
        const float2 o2 = *reinterpret_cast<const float2*>(
            proj + (size_t)row * NPROJ + 256 + head * 32 + 2 * i);
        const float x = rx + o2.x;
        const float y = ry + o2.y;

        const float xf = floorf(x), yf = floorf(y);
        const int x0 = (int)xf, y0 = (int)yf;
        const float lx = x - xf, ly = y - yf;

        const bool yin0 = (y0 >= 0) & (y0 < Hl);
        const bool yin1 = (y0 + 1 >= 0) & (y0 + 1 < Hl);
        const bool xin0 = (x0 >= 0) & (x0 < Wl);
        const bool xin1 = (x0 + 1 >= 0) & (x0 + 1 < Wl);

        const int base = vbase + c_start[l];
        const int r0 = (base + y0 * Wl) * NPROJ + head * 32;
        const int r1 = r0 + Wl * NPROJ;

        IW c0, c1, c2, c3;
        c0.idx = (yin0 && xin0) ? r0 + x0 * NPROJ       : -1;
        c1.idx = (yin0 && xin1) ? r0 + (x0 + 1) * NPROJ : -1;
        c2.idx = (yin1 && xin0) ? r1 + x0 * NPROJ       : -1;
        c3.idx = (yin1 && xin1) ? r1 + (x0 + 1) * NPROJ : -1;
        c0.w = (1.f - ly) * (1.f - lx) * w;
        c1.w = (1.f - ly) * lx * w;
        c2.w = ly * (1.f - lx) * w;
        c3.w = ly * lx * w;
        s_iw[tid][0] = c0;
        s_iw[tid][1] = c1;
        s_iw[tid][2] = c2;
        s_iw[tid][3] = c3;
    }
    __syncthreads();

    const int head = tid >> 5;
    const int lane = tid & 31;
    const int g    = lane >> 3;
    const int sub  = lane & 7;

    int   ji[16];
    float wi[16];
#pragma unroll
    for (int i = 0; i < 16; i++) {
        const IW p = s_iw[head * 16 + i][g];
        ji[i] = p.idx;
        wi[i] = p.w;
    }

    float4 a = make_float4(0.f, 0.f, 0.f, 0.f);
#pragma unroll
    for (int b = 0; b < 2; b++) {
        float4 v[8];
#pragma unroll
        for (int j = 0; j < 8; j++) {
            const int id = ji[b * 8 + j];
            v[j] = (id >= 0)
                 ? *reinterpret_cast<const float4*>(proj + id + (sub << 2))
                 : make_float4(0.f, 0.f, 0.f, 0.f);
        }
#pragma unroll
        for (int j = 0; j < 8; j++) {
            const float w = wi[b * 8 + j];
            a.x = fmaf(w, v[j].x, a.x);
            a.y = fmaf(w, v[j].y, a.y);
            a.z = fmaf(w, v[j].z, a.z);
            a.w = fmaf(w, v[j].w, a.w);
        }
    }
#pragma unroll
    for (int o = 8; o <= 16; o <<= 1) {
        a.x += __shfl_xor_sync(0xffffffffu, a.x, o);
        a.y += __shfl_xor_sync(0xffffffffu, a.y, o);
        a.z += __shfl_xor_sync(0xffffffffu, a.z, o);
        a.w += __shfl_xor_sync(0xffffffffu, a.w, o);
    }
    if (lane < 8)
        *reinterpret_cast<float4*>(acc + (size_t)row * 256 + head * 32 + (sub << 2)) = a;
}

// ---------------- launch ----------------
extern "C" void kernel_launch(void* const* d_in, const int* in_sizes, int n_in,
                              void* d_out, int out_size) {
    const float* query  = (const float*)d_in[0];
    const float* refpts = (const float*)d_in[1];
    const float* Wv   = (const float*)d_in[3];
    const float* bv   = (const float*)d_in[4];
    const float* Woff = (const float*)d_in[5];
    const float* boff = (const float*)d_in[6];
    const float* Wat  = (const float*)d_in[7];
    const float* bat  = (const float*)d_in[8];
    const float* Wout = (const float*)d_in[9];
    const float* bout = (const float*)d_in[10];
    float* out = (float*)d_out;

    float *p_proj, *p_acc, *p_Wcat, *p_bcat;
    cudaGetSymbolAddress((void**)&p_proj, g_proj);
    cudaGetSymbolAddress((void**)&p_acc,  g_acc);
    cudaGetSymbolAddress((void**)&p_Wcat, g_Wcat);
    cudaGetSymbolAddress((void**)&p_bcat, g_bcat);

    cudaFuncSetAttribute(gemm_tf32_kernel,
                         cudaFuncAttributeMaxDynamicSharedMemorySize, SMEM_GEMM);

    const int M  = M_TOT;
    const int gy = (M + 127) / 128;   // 208

    pack_kernel<<<(EMBED * NPROJ + 255) / 256, 256>>>(Wv, Woff, Wat, bv, boff, bat,
                                                      p_Wcat, p_bcat);

    gemm_tf32_kernel<<<dim3(NPROJ / 128, gy), 256, SMEM_GEMM>>>(
        query, EMBED, p_Wcat, NPROJ, p_bcat, nullptr, p_proj, NPROJ, M);

    msda_sample_kernel<<<M, HEADS * 32>>>(refpts, p_proj, p_acc);

    gemm_tf32_kernel<<<dim3(2, gy), 256, SMEM_GEMM>>>(
        p_acc, EMBED, Wout, EMBED, bout, query, out, EMBED, M);
}

// round 10
// speedup vs baseline: 2.1378x; 1.0242x over previous
#include <cuda_runtime.h>
#include <cstdint>

// ---------------- problem constants ----------------
#define NQ      13294
#define BS      2
#define M_TOT   (BS * NQ)      // 26588
#define EMBED   256
#define HEADS   8
#define LEVELS  4
#define POINTS  4
#define NPROJ   640            // 256 (value) + 256 (off) + 128 (attn)

__device__ __constant__ int c_Wl[LEVELS]    = {100, 50, 25, 13};
__device__ __constant__ int c_Hl[LEVELS]    = {100, 50, 25, 13};
__device__ __constant__ int c_start[LEVELS] = {0, 10000, 12500, 13125};

// ---------------- scratch ----------------
__device__ float g_proj[(size_t)M_TOT * NPROJ];  // [value(256) | off(256) | attn(128)]
__device__ float g_acc [(size_t)M_TOT * EMBED];
__device__ float g_Wcat[(size_t)EMBED * NPROJ];
__device__ float g_bcat[NPROJ];

// ---------------- pack kernel ----------------
__global__ void pack_kernel(const float* __restrict__ Wv, const float* __restrict__ Woff,
                            const float* __restrict__ Wat, const float* __restrict__ bv,
                            const float* __restrict__ boff, const float* __restrict__ bat,
                            float* __restrict__ Wcat, float* __restrict__ bcat) {
    const int idx = blockIdx.x * blockDim.x + threadIdx.x;
    if (idx < EMBED * NPROJ) {
        const int k = idx / NPROJ;
        const int n = idx - k * NPROJ;
        float v;
        if (n < 256)      v = Wv  [k * 256 + n];
        else if (n < 512) v = Woff[k * 256 + (n - 256)];
        else              v = Wat [k * 128 + (n - 512)];
        Wcat[idx] = v;
    }
    if (idx < NPROJ) {
        float b;
        if (idx < 256)      b = bv  [idx];
        else if (idx < 512) b = boff[idx - 256];
        else                b = bat [idx - 512];
        bcat[idx] = b;
    }
}

// ---------------- tf32 GEMM: K-chunk 32, 3-stage cp.async, 1 sync/step ----------------
#define GTK     32
#define NKS     (EMBED / GTK)    // 8
#define LDA     36               // 32 + 4 pad: bank = (36*grp + k) mod 32 = permutation
#define LDB     136              // 128 + 8 pad
#define STAGES  3
#define A_STG   (128 * LDA)      // floats per A stage
#define B_STG   (GTK * LDB)      // floats per B stage
#define SMEM_GEMM ((STAGES * (A_STG + B_STG)) * 4)   // 107520 bytes

__device__ __forceinline__ uint32_t smem_u32(const void* p) {
    return (uint32_t)__cvta_generic_to_shared(p);
}
__device__ __forceinline__ void cp_async16(uint32_t dst, const void* src, uint32_t sz) {
    asm volatile("cp.async.cg.shared.global [%0], [%1], 16, %2;"
                 :: "r"(dst), "l"(src), "r"(sz));
}
__device__ __forceinline__ uint32_t f2tf32(float f) {
    uint32_t r;
    asm("cvt.rna.tf32.f32 %0, %1;" : "=r"(r) : "f"(f));
    return r;
}

__global__ void __launch_bounds__(256)
gemm_tf32_kernel(const float* __restrict__ A, int lda,
                 const float* __restrict__ B, int ldb,
                 const float* __restrict__ bias,
                 const float* __restrict__ resid,
                 float* __restrict__ C, int ldc,
                 int M) {
    extern __shared__ __align__(16) float smem[];
    float* sA = smem;
    float* sB = smem + STAGES * A_STG;

    const int tid  = threadIdx.x;
    const int wid  = tid >> 5;
    const int lane = tid & 31;
    const int m_w  = (wid >> 2) * 64;
    const int n_w  = (wid & 3) * 32;
    const int m0   = blockIdx.y * 128;
    const int n0   = blockIdx.x * 128;

    const int grp = lane >> 2;
    const int tig = lane & 3;

    float acc[4][4][4];
#pragma unroll
    for (int i = 0; i < 4; i++)
#pragma unroll
        for (int j = 0; j < 4; j++)
#pragma unroll
            for (int r = 0; r < 4; r++) acc[i][j][r] = 0.f;

    // per-stage cp.async: A = 1024 chunks of 16B (128r x 8), B = 1024 (32r x 32)
    auto load_stage = [&](int ks) {
        const int buf = ks % STAGES;
        const int k0  = ks * GTK;
        float* dA = sA + buf * A_STG;
        float* dB = sB + buf * B_STG;
#pragma unroll
        for (int c = 0; c < 4; c++) {
            const int ch  = tid + c * 256;
            const int row = ch >> 3;
            const int col = ch & 7;           // float4 index
            const int gm  = m0 + row;
            cp_async16(smem_u32(&dA[row * LDA + col * 4]),
                       A + (size_t)gm * lda + k0 + col * 4, gm < M ? 16u : 0u);
        }
#pragma unroll
        for (int c = 0; c < 4; c++) {
            const int ch  = tid + c * 256;
            const int row = ch >> 5;
            const int col = ch & 31;
            cp_async16(smem_u32(&dB[row * LDB + col * 4]),
                       B + (size_t)(k0 + row) * ldb + n0 + col * 4, 16u);
        }
    };

    // prologue: 2 stages in flight
#pragma unroll
    for (int s = 0; s < STAGES - 1; s++) {
        load_stage(s);
        asm volatile("cp.async.commit_group;" ::: "memory");
    }

    auto load_frags = [&](const float* cA, const float* cB, int kb,
                          uint32_t af[4][4], uint32_t bf[4][2]) {
#pragma unroll
        for (int mt = 0; mt < 4; mt++) {
            const int mrow = m_w + mt * 16 + grp;
            af[mt][0] = f2tf32(cA[ mrow      * LDA + kb + tig]);
            af[mt][1] = f2tf32(cA[(mrow + 8) * LDA + kb + tig]);
            af[mt][2] = f2tf32(cA[ mrow      * LDA + kb + tig + 4]);
            af[mt][3] = f2tf32(cA[(mrow + 8) * LDA + kb + tig + 4]);
        }
#pragma unroll
        for (int nt = 0; nt < 4; nt++) {
            const int ncol = n_w + nt * 8 + grp;
            bf[nt][0] = f2tf32(cB[(kb + tig)     * LDB + ncol]);
            bf[nt][1] = f2tf32(cB[(kb + tig + 4) * LDB + ncol]);
        }
    };
    auto do_mma = [&](uint32_t af[4][4], uint32_t bf[4][2]) {
#pragma unroll
        for (int mt = 0; mt < 4; mt++)
#pragma unroll
            for (int nt = 0; nt < 4; nt++) {
                asm volatile(
                    "mma.sync.aligned.m16n8k8.row.col.f32.tf32.tf32.f32 "
                    "{%0,%1,%2,%3}, {%4,%5,%6,%7}, {%8,%9}, {%0,%1,%2,%3};"
                    : "+f"(acc[mt][nt][0]), "+f"(acc[mt][nt][1]),
                      "+f"(acc[mt][nt][2]), "+f"(acc[mt][nt][3])
                    : "r"(af[mt][0]), "r"(af[mt][1]), "r"(af[mt][2]), "r"(af[mt][3]),
                      "r"(bf[nt][0]), "r"(bf[nt][1]));
            }
    };

    uint32_t af2[2][4][4], bf2[2][4][2];

    for (int ks = 0; ks < NKS; ks++) {
        // stage ks guaranteed complete after leaving at most 1 group pending
        asm volatile("cp.async.wait_group 1;" ::: "memory");
        __syncthreads();   // single barrier per k-step

        if (ks + STAGES - 1 < NKS) load_stage(ks + STAGES - 1);
        asm volatile("cp.async.commit_group;" ::: "memory");

        const float* cA = sA + (ks % STAGES) * A_STG;
        const float* cB = sB + (ks % STAGES) * B_STG;

        load_frags(cA, cB, 0, af2[0], bf2[0]);
#pragma unroll
        for (int sub = 0; sub < 4; sub++) {
            const int p = sub & 1;
            if (sub < 3) load_frags(cA, cB, (sub + 1) * 8, af2[p ^ 1], bf2[p ^ 1]);
            do_mma(af2[p], bf2[p]);
        }
    }

    // epilogue
#pragma unroll
    for (int mt = 0; mt < 4; mt++) {
#pragma unroll
        for (int nt = 0; nt < 4; nt++) {
            const int gm = m0 + m_w + mt * 16 + grp;
            const int gn = n0 + n_w + nt * 8 + tig * 2;
            const float b0 = bias[gn], b1 = bias[gn + 1];
            if (gm < M) {
                float v0 = acc[mt][nt][0] + b0;
                float v1 = acc[mt][nt][1] + b1;
                if (resid) {
                    v0 += resid[(size_t)gm * ldc + gn];
                    v1 += resid[(size_t)gm * ldc + gn + 1];
                }
                C[(size_t)gm * ldc + gn]     = v0;
                C[(size_t)gm * ldc + gn + 1] = v1;
            }
            if (gm + 8 < M) {
                float v2 = acc[mt][nt][2] + b0;
                float v3 = acc[mt][nt][3] + b1;
                if (resid) {
                    v2 += resid[(size_t)(gm + 8) * ldc + gn];
                    v3 += resid[(size_t)(gm + 8) * ldc + gn + 1];
                }
                C[(size_t)(gm + 8) * ldc + gn]     = v2;
                C[(size_t)(gm + 8) * ldc + gn + 1] = v3;
            }
        }
    }
}

// ---------------- sampling kernel (unchanged) ----------------
struct IW { int idx; float w; };

__global__ void msda_sample_kernel(const float* __restrict__ ref,
                                   const float* __restrict__ proj,
                                   float* __restrict__ acc) {
    __shared__ IW s_iw[128][4];

    const int row = blockIdx.x;
    const int tid = threadIdx.x;
    const int vbase = (row >= NQ) ? NQ : 0;

    if (tid < 128) {
        const int head = tid >> 4;
        const int i    = tid & 15;
        const int l    = i >> 2;
        const int Wl = c_Wl[l], Hl = c_Hl[l];

        float lg = __ldg(proj + (size_t)row * NPROJ + 512 + tid);
        float mx = lg;
#pragma unroll
        for (int o = 8; o >= 1; o >>= 1)
            mx = fmaxf(mx, __shfl_xor_sync(0xffffffffu, mx, o, 16));
        float e = __expf(lg - mx);
        float s = e;
#pragma unroll
        for (int o = 8; o >= 1; o >>= 1)
            s += __shfl_xor_sync(0xffffffffu, s, o, 16);
        const float w = e * __frcp_rn(s);

        const float rx = __ldg(ref + (size_t)row * 8 + 2 * l + 0) * (float)Wl - 0.5f;
        const float ry = __ldg(ref + (size_t)row * 8 + 2 * l + 1) * (float)Hl - 0.5f;
        const float2 o2 = *reinterpret_cast<const float2*>(
            proj + (size_t)row * NPROJ + 256 + head * 32 + 2 * i);
        const float x = rx + o2.x;
        const float y = ry + o2.y;

        const float xf = floorf(x), yf = floorf(y);
        const int x0 = (int)xf, y0 = (int)yf;
        const float lx = x - xf, ly = y - yf;

        const bool yin0 = (y0 >= 0) & (y0 < Hl);
        const bool yin1 = (y0 + 1 >= 0) & (y0 + 1 < Hl);
        const bool xin0 = (x0 >= 0) & (x0 < Wl);
        const bool xin1 = (x0 + 1 >= 0) & (x0 + 1 < Wl);

        const int base = vbase + c_start[l];
        const int r0 = (base + y0 * Wl) * NPROJ + head * 32;
        const int r1 = r0 + Wl * NPROJ;

        IW c0, c1, c2, c3;
        c0.idx = (yin0 && xin0) ? r0 + x0 * NPROJ       : -1;
        c1.idx = (yin0 && xin1) ? r0 + (x0 + 1) * NPROJ : -1;
        c2.idx = (yin1 && xin0) ? r1 + x0 * NPROJ       : -1;
        c3.idx = (yin1 && xin1) ? r1 + (x0 + 1) * NPROJ : -1;
        c0.w = (1.f - ly) * (1.f - lx) * w;
        c1.w = (1.f - ly) * lx * w;
        c2.w = ly * (1.f - lx) * w;
        c3.w = ly * lx * w;
        s_iw[tid][0] = c0;
        s_iw[tid][1] = c1;
        s_iw[tid][2] = c2;
        s_iw[tid][3] = c3;
    }
    __syncthreads();

    const int head = tid >> 5;
    const int lane = tid & 31;
    const int g    = lane >> 3;
    const int sub  = lane & 7;

    int   ji[16];
    float wi[16];
#pragma unroll
    for (int i = 0; i < 16; i++) {
        const IW p = s_iw[head * 16 + i][g];
        ji[i] = p.idx;
        wi[i] = p.w;
    }

    float4 a = make_float4(0.f, 0.f, 0.f, 0.f);
#pragma unroll
    for (int b = 0; b < 2; b++) {
        float4 v[8];
#pragma unroll
        for (int j = 0; j < 8; j++) {
            const int id = ji[b * 8 + j];
            v[j] = (id >= 0)
                 ? *reinterpret_cast<const float4*>(proj + id + (sub << 2))
                 : make_float4(0.f, 0.f, 0.f, 0.f);
        }
#pragma unroll
        for (int j = 0; j < 8; j++) {
            const float w = wi[b * 8 + j];
            a.x = fmaf(w, v[j].x, a.x);
            a.y = fmaf(w, v[j].y, a.y);
            a.z = fmaf(w, v[j].z, a.z);
            a.w = fmaf(w, v[j].w, a.w);
        }
    }
#pragma unroll
    for (int o = 8; o <= 16; o <<= 1) {
        a.x += __shfl_xor_sync(0xffffffffu, a.x, o);
        a.y += __shfl_xor_sync(0xffffffffu, a.y, o);
        a.z += __shfl_xor_sync(0xffffffffu, a.z, o);
        a.w += __shfl_xor_sync(0xffffffffu, a.w, o);
    }
    if (lane < 8)
        *reinterpret_cast<float4*>(acc + (size_t)row * 256 + head * 32 + (sub << 2)) = a;
}

// ---------------- launch ----------------
extern "C" void kernel_launch(void* const* d_in, const int* in_sizes, int n_in,
                              void* d_out, int out_size) {
    const float* query  = (const float*)d_in[0];
    const float* refpts = (const float*)d_in[1];
    const float* Wv   = (const float*)d_in[3];
    const float* bv   = (const float*)d_in[4];
    const float* Woff = (const float*)d_in[5];
    const float* boff = (const float*)d_in[6];
    const float* Wat  = (const float*)d_in[7];
    const float* bat  = (const float*)d_in[8];
    const float* Wout = (const float*)d_in[9];
    const float* bout = (const float*)d_in[10];
    float* out = (float*)d_out;

    float *p_proj, *p_acc, *p_Wcat, *p_bcat;
    cudaGetSymbolAddress((void**)&p_proj, g_proj);
    cudaGetSymbolAddress((void**)&p_acc,  g_acc);
    cudaGetSymbolAddress((void**)&p_Wcat, g_Wcat);
    cudaGetSymbolAddress((void**)&p_bcat, g_bcat);

    cudaFuncSetAttribute(gemm_tf32_kernel,
                         cudaFuncAttributeMaxDynamicSharedMemorySize, SMEM_GEMM);

    const int M  = M_TOT;
    const int gy = (M + 127) / 128;   // 208

    pack_kernel<<<(EMBED * NPROJ + 255) / 256, 256>>>(Wv, Woff, Wat, bv, boff, bat,
                                                      p_Wcat, p_bcat);

    gemm_tf32_kernel<<<dim3(NPROJ / 128, gy), 256, SMEM_GEMM>>>(
        query, EMBED, p_Wcat, NPROJ, p_bcat, nullptr, p_proj, NPROJ, M);

    msda_sample_kernel<<<M, HEADS * 32>>>(refpts, p_proj, p_acc);

    gemm_tf32_kernel<<<dim3(2, gy), 256, SMEM_GEMM>>>(
        p_acc, EMBED, Wout, EMBED, bout, query, out, EMBED, M);
}

// round 11
// speedup vs baseline: 2.1553x; 1.0082x over previous
#include <cuda_runtime.h>
#include <cstdint>

// ---------------- problem constants ----------------
#define NQ      13294
#define BS      2
#define M_TOT   (BS * NQ)      // 26588
#define EMBED   256
#define HEADS   8
#define LEVELS  4
#define POINTS  4
#define NPROJ   640            // 256 (value) + 256 (off) + 128 (attn)

__device__ __constant__ int c_Wl[LEVELS]    = {100, 50, 25, 13};
__device__ __constant__ int c_Hl[LEVELS]    = {100, 50, 25, 13};
__device__ __constant__ int c_start[LEVELS] = {0, 10000, 12500, 13125};

// ---------------- scratch ----------------
__device__ float g_proj   [(size_t)M_TOT * NPROJ];  // [value(256) | off(256) | attn(128)]
__device__ float g_acc    [(size_t)M_TOT * EMBED];  // tf32-rounded at producer
__device__ float g_query_t[(size_t)M_TOT * EMBED];  // tf32-rounded query
__device__ float g_Wcat   [(size_t)EMBED * NPROJ];  // tf32-rounded
__device__ float g_Wout_t [(size_t)EMBED * EMBED];  // tf32-rounded
__device__ float g_bcat   [NPROJ];

__device__ __forceinline__ uint32_t f2tf32(float f) {
    uint32_t r;
    asm("cvt.rna.tf32.f32 %0, %1;" : "=r"(r) : "f"(f));
    return r;
}
__device__ __forceinline__ float tf32r(float f) { return __uint_as_float(f2tf32(f)); }

// ---------------- pack kernel (weights pre-rounded to tf32 bits) ----------------
__global__ void pack_kernel(const float* __restrict__ Wv, const float* __restrict__ Woff,
                            const float* __restrict__ Wat, const float* __restrict__ bv,
                            const float* __restrict__ boff, const float* __restrict__ bat,
                            float* __restrict__ Wcat, float* __restrict__ bcat) {
    const int idx = blockIdx.x * blockDim.x + threadIdx.x;
    if (idx < EMBED * NPROJ) {
        const int k = idx / NPROJ;
        const int n = idx - k * NPROJ;
        float v;
        if (n < 256)      v = Wv  [k * 256 + n];
        else if (n < 512) v = Woff[k * 256 + (n - 256)];
        else              v = Wat [k * 128 + (n - 512)];
        Wcat[idx] = tf32r(v);
    }
    if (idx < NPROJ) {
        float b;
        if (idx < 256)      b = bv  [idx];
        else if (idx < 512) b = boff[idx - 256];
        else                b = bat [idx - 512];
        bcat[idx] = b;
    }
}

// tf32-round a float buffer (vectorized), n4 = count/4
__global__ void trunc_kernel(const float* __restrict__ src, float* __restrict__ dst, int n4) {
    const int idx = blockIdx.x * blockDim.x + threadIdx.x;
    if (idx >= n4) return;
    float4 v = reinterpret_cast<const float4*>(src)[idx];
    v.x = tf32r(v.x); v.y = tf32r(v.y); v.z = tf32r(v.z); v.w = tf32r(v.w);
    reinterpret_cast<float4*>(dst)[idx] = v;
}

// ---------------- tf32 GEMM: K-chunk 32, 3-stage cp.async, 1 sync/step ----------------
// Operands are pre-rounded tf32 bit patterns: inner loop = LDS + MMA only.
#define GTK     32
#define NKS     (EMBED / GTK)    // 8
#define LDA     36               // 32 + 4 pad: conflict-free A fragment loads
#define LDB     136              // 128 + 8 pad
#define STAGES  3
#define A_STG   (128 * LDA)
#define B_STG   (GTK * LDB)
#define SMEM_GEMM ((STAGES * (A_STG + B_STG)) * 4)   // 107520 bytes

__device__ __forceinline__ uint32_t smem_u32(const void* p) {
    return (uint32_t)__cvta_generic_to_shared(p);
}
__device__ __forceinline__ void cp_async16(uint32_t dst, const void* src, uint32_t sz) {
    asm volatile("cp.async.cg.shared.global [%0], [%1], 16, %2;"
                 :: "r"(dst), "l"(src), "r"(sz));
}

__global__ void __launch_bounds__(256)
gemm_tf32_kernel(const float* __restrict__ A, int lda,
                 const float* __restrict__ B, int ldb,
                 const float* __restrict__ bias,
                 const float* __restrict__ resid,
                 float* __restrict__ C, int ldc,
                 int M) {
    extern __shared__ __align__(16) float smem[];
    float* sA = smem;
    float* sB = smem + STAGES * A_STG;

    const int tid  = threadIdx.x;
    const int wid  = tid >> 5;
    const int lane = tid & 31;
    const int m_w  = (wid >> 2) * 64;
    const int n_w  = (wid & 3) * 32;
    const int m0   = blockIdx.y * 128;
    const int n0   = blockIdx.x * 128;

    const int grp = lane >> 2;
    const int tig = lane & 3;

    float acc[4][4][4];
#pragma unroll
    for (int i = 0; i < 4; i++)
#pragma unroll
        for (int j = 0; j < 4; j++)
#pragma unroll
            for (int r = 0; r < 4; r++) acc[i][j][r] = 0.f;

    auto load_stage = [&](int ks) {
        const int buf = ks % STAGES;
        const int k0  = ks * GTK;
        float* dA = sA + buf * A_STG;
        float* dB = sB + buf * B_STG;
#pragma unroll
        for (int c = 0; c < 4; c++) {
            const int ch  = tid + c * 256;
            const int row = ch >> 3;
            const int col = ch & 7;
            const int gm  = m0 + row;
            cp_async16(smem_u32(&dA[row * LDA + col * 4]),
                       A + (size_t)gm * lda + k0 + col * 4, gm < M ? 16u : 0u);
        }
#pragma unroll
        for (int c = 0; c < 4; c++) {
            const int ch  = tid + c * 256;
            const int row = ch >> 5;
            const int col = ch & 31;
            cp_async16(smem_u32(&dB[row * LDB + col * 4]),
                       B + (size_t)(k0 + row) * ldb + n0 + col * 4, 16u);
        }
    };

#pragma unroll
    for (int s = 0; s < STAGES - 1; s++) {
        load_stage(s);
        asm volatile("cp.async.commit_group;" ::: "memory");
    }

    // raw-bit fragment loads (operands already tf32-rounded)
    auto load_frags = [&](const float* cA, const float* cB, int kb,
                          uint32_t af[4][4], uint32_t bf[4][2]) {
#pragma unroll
        for (int mt = 0; mt < 4; mt++) {
            const int mrow = m_w + mt * 16 + grp;
            af[mt][0] = __float_as_uint(cA[ mrow      * LDA + kb + tig]);
            af[mt][1] = __float_as_uint(cA[(mrow + 8) * LDA + kb + tig]);
            af[mt][2] = __float_as_uint(cA[ mrow      * LDA + kb + tig + 4]);
            af[mt][3] = __float_as_uint(cA[(mrow + 8) * LDA + kb + tig + 4]);
        }
#pragma unroll
        for (int nt = 0; nt < 4; nt++) {
            const int ncol = n_w + nt * 8 + grp;
            bf[nt][0] = __float_as_uint(cB[(kb + tig)     * LDB + ncol]);
            bf[nt][1] = __float_as_uint(cB[(kb + tig + 4) * LDB + ncol]);
        }
    };
    auto do_mma = [&](uint32_t af[4][4], uint32_t bf[4][2]) {
#pragma unroll
        for (int mt = 0; mt < 4; mt++)
#pragma unroll
            for (int nt = 0; nt < 4; nt++) {
                asm volatile(
                    "mma.sync.aligned.m16n8k8.row.col.f32.tf32.tf32.f32 "
                    "{%0,%1,%2,%3}, {%4,%5,%6,%7}, {%8,%9}, {%0,%1,%2,%3};"
                    : "+f"(acc[mt][nt][0]), "+f"(acc[mt][nt][1]),
                      "+f"(acc[mt][nt][2]), "+f"(acc[mt][nt][3])
                    : "r"(af[mt][0]), "r"(af[mt][1]), "r"(af[mt][2]), "r"(af[mt][3]),
                      "r"(bf[nt][0]), "r"(bf[nt][1]));
            }
    };

    uint32_t af2[2][4][4], bf2[2][4][2];

    for (int ks = 0; ks < NKS; ks++) {
        asm volatile("cp.async.wait_group 1;" ::: "memory");
        __syncthreads();

        if (ks + STAGES - 1 < NKS) load_stage(ks + STAGES - 1);
        asm volatile("cp.async.commit_group;" ::: "memory");

        const float* cA = sA + (ks % STAGES) * A_STG;
        const float* cB = sB + (ks % STAGES) * B_STG;

        load_frags(cA, cB, 0, af2[0], bf2[0]);
#pragma unroll
        for (int sub = 0; sub < 4; sub++) {
            const int p = sub & 1;
            if (sub < 3) load_frags(cA, cB, (sub + 1) * 8, af2[p ^ 1], bf2[p ^ 1]);
            do_mma(af2[p], bf2[p]);
        }
    }

    // epilogue
#pragma unroll
    for (int mt = 0; mt < 4; mt++) {
#pragma unroll
        for (int nt = 0; nt < 4; nt++) {
            const int gm = m0 + m_w + mt * 16 + grp;
            const int gn = n0 + n_w + nt * 8 + tig * 2;
            const float b0 = bias[gn], b1 = bias[gn + 1];
            if (gm < M) {
                float v0 = acc[mt][nt][0] + b0;
                float v1 = acc[mt][nt][1] + b1;
                if (resid) {
                    v0 += resid[(size_t)gm * ldc + gn];
                    v1 += resid[(size_t)gm * ldc + gn + 1];
                }
                C[(size_t)gm * ldc + gn]     = v0;
                C[(size_t)gm * ldc + gn + 1] = v1;
            }
            if (gm + 8 < M) {
                float v2 = acc[mt][nt][2] + b0;
                float v3 = acc[mt][nt][3] + b1;
                if (resid) {
                    v2 += resid[(size_t)(gm + 8) * ldc + gn];
                    v3 += resid[(size_t)(gm + 8) * ldc + gn + 1];
                }
                C[(size_t)(gm + 8) * ldc + gn]     = v2;
                C[(size_t)(gm + 8) * ldc + gn + 1] = v3;
            }
        }
    }
}

// ---------------- sampling kernel (acc stored tf32-rounded) ----------------
struct IW { int idx; float w; };

__global__ void msda_sample_kernel(const float* __restrict__ ref,
                                   const float* __restrict__ proj,
                                   float* __restrict__ acc) {
    __shared__ IW s_iw[128][4];

    const int row = blockIdx.x;
    const int tid = threadIdx.x;
    const int vbase = (row >= NQ) ? NQ : 0;

    if (tid < 128) {
        const int head = tid >> 4;
        const int i    = tid & 15;
        const int l    = i >> 2;
        const int Wl = c_Wl[l], Hl = c_Hl[l];

        float lg = __ldg(proj + (size_t)row * NPROJ + 512 + tid);
        float mx = lg;
#pragma unroll
        for (int o = 8; o >= 1; o >>= 1)
            mx = fmaxf(mx, __shfl_xor_sync(0xffffffffu, mx, o, 16));
        float e = __expf(lg - mx);
        float s = e;
#pragma unroll
        for (int o = 8; o >= 1; o >>= 1)
            s += __shfl_xor_sync(0xffffffffu, s, o, 16);
        const float w = e * __frcp_rn(s);

        const float rx = __ldg(ref + (size_t)row * 8 + 2 * l + 0) * (float)Wl - 0.5f;
        const float ry = __ldg(ref + (size_t)row * 8 + 2 * l + 1) * (float)Hl - 0.5f;
        const float2 o2 = *reinterpret_cast<const float2*>(
            proj + (size_t)row * NPROJ + 256 + head * 32 + 2 * i);
        const float x = rx + o2.x;
        const float y = ry + o2.y;

        const float xf = floorf(x), yf = floorf(y);
        const int x0 = (int)xf, y0 = (int)yf;
        const float lx = x - xf, ly = y - yf;

        const bool yin0 = (y0 >= 0) & (y0 < Hl);
        const bool yin1 = (y0 + 1 >= 0) & (y0 + 1 < Hl);
        const bool xin0 = (x0 >= 0) & (x0 < Wl);
        const bool xin1 = (x0 + 1 >= 0) & (x0 + 1 < Wl);

        const int base = vbase + c_start[l];
        const int r0 = (base + y0 * Wl) * NPROJ + head * 32;
        const int r1 = r0 + Wl * NPROJ;

        IW c0, c1, c2, c3;
        c0.idx = (yin0 && xin0) ? r0 + x0 * NPROJ       : -1;
        c1.idx = (yin0 && xin1) ? r0 + (x0 + 1) * NPROJ : -1;
        c2.idx = (yin1 && xin0) ? r1 + x0 * NPROJ       : -1;
        c3.idx = (yin1 && xin1) ? r1 + (x0 + 1) * NPROJ : -1;
        c0.w = (1.f - ly) * (1.f - lx) * w;
        c1.w = (1.f - ly) * lx * w;
        c2.w = ly * (1.f - lx) * w;
        c3.w = ly * lx * w;
        s_iw[tid][0] = c0;
        s_iw[tid][1] = c1;
        s_iw[tid][2] = c2;
        s_iw[tid][3] = c3;
    }
    __syncthreads();

    const int head = tid >> 5;
    const int lane = tid & 31;
    const int g    = lane >> 3;
    const int sub  = lane & 7;

    int   ji[16];
    float wi[16];
#pragma unroll
    for (int i = 0; i < 16; i++) {
        const IW p = s_iw[head * 16 + i][g];
        ji[i] = p.idx;
        wi[i] = p.w;
    }

    float4 a = make_float4(0.f, 0.f, 0.f, 0.f);
#pragma unroll
    for (int b = 0; b < 2; b++) {
        float4 v[8];
#pragma unroll
        for (int j = 0; j < 8; j++) {
            const int id = ji[b * 8 + j];
            v[j] = (id >= 0)
                 ? *reinterpret_cast<const float4*>(proj + id + (sub << 2))
                 : make_float4(0.f, 0.f, 0.f, 0.f);
        }
#pragma unroll
        for (int j = 0; j < 8; j++) {
            const float w = wi[b * 8 + j];
            a.x = fmaf(w, v[j].x, a.x);
            a.y = fmaf(w, v[j].y, a.y);
            a.z = fmaf(w, v[j].z, a.z);
            a.w = fmaf(w, v[j].w, a.w);
        }
    }
#pragma unroll
    for (int o = 8; o <= 16; o <<= 1) {
        a.x += __shfl_xor_sync(0xffffffffu, a.x, o);
        a.y += __shfl_xor_sync(0xffffffffu, a.y, o);
        a.z += __shfl_xor_sync(0xffffffffu, a.z, o);
        a.w += __shfl_xor_sync(0xffffffffu, a.w, o);
    }
    if (lane < 8) {
        // pre-round to tf32: g_acc is consumed only as GEMM A operand
        a.x = tf32r(a.x); a.y = tf32r(a.y); a.z = tf32r(a.z); a.w = tf32r(a.w);
        *reinterpret_cast<float4*>(acc + (size_t)row * 256 + head * 32 + (sub << 2)) = a;
    }
}

// ---------------- launch ----------------
extern "C" void kernel_launch(void* const* d_in, const int* in_sizes, int n_in,
                              void* d_out, int out_size) {
    const float* query  = (const float*)d_in[0];
    const float* refpts = (const float*)d_in[1];
    const float* Wv   = (const float*)d_in[3];
    const float* bv   = (const float*)d_in[4];
    const float* Woff = (const float*)d_in[5];
    const float* boff = (const float*)d_in[6];
    const float* Wat  = (const float*)d_in[7];
    const float* bat  = (const float*)d_in[8];
    const float* Wout = (const float*)d_in[9];
    const float* bout = (const float*)d_in[10];
    float* out = (float*)d_out;

    float *p_proj, *p_acc, *p_qt, *p_Wcat, *p_Wout_t, *p_bcat;
    cudaGetSymbolAddress((void**)&p_proj,   g_proj);
    cudaGetSymbolAddress((void**)&p_acc,    g_acc);
    cudaGetSymbolAddress((void**)&p_qt,     g_query_t);
    cudaGetSymbolAddress((void**)&p_Wcat,   g_Wcat);
    cudaGetSymbolAddress((void**)&p_Wout_t, g_Wout_t);
    cudaGetSymbolAddress((void**)&p_bcat,   g_bcat);

    cudaFuncSetAttribute(gemm_tf32_kernel,
                         cudaFuncAttributeMaxDynamicSharedMemorySize, SMEM_GEMM);

    const int M  = M_TOT;
    const int gy = (M + 127) / 128;   // 208

    // operand prep (tf32-rounded copies)
    pack_kernel<<<(EMBED * NPROJ + 255) / 256, 256>>>(Wv, Woff, Wat, bv, boff, bat,
                                                      p_Wcat, p_bcat);
    trunc_kernel<<<(M * EMBED / 4 + 255) / 256, 256>>>(query, p_qt, M * EMBED / 4);
    trunc_kernel<<<(EMBED * EMBED / 4 + 255) / 256, 256>>>(Wout, p_Wout_t, EMBED * EMBED / 4);

    // fused projection GEMM: M x 640
    gemm_tf32_kernel<<<dim3(NPROJ / 128, gy), 256, SMEM_GEMM>>>(
        p_qt, EMBED, p_Wcat, NPROJ, p_bcat, nullptr, p_proj, NPROJ, M);

    // deformable sampling (+ fused softmax, tf32-rounded acc)
    msda_sample_kernel<<<M, HEADS * 32>>>(refpts, p_proj, p_acc);

    // output projection + bias + residual (residual = ORIGINAL fp32 query)
    gemm_tf32_kernel<<<dim3(2, gy), 256, SMEM_GEMM>>>(
        p_acc, EMBED, p_Wout_t, EMBED, bout, query, out, EMBED, M);
}